// round 13
// baseline (speedup 1.0000x reference)
#include <cuda_runtime.h>
#include <cuda_bf16.h>
#include <math.h>
#include <stdint.h>

// Problem constants
#define BATCH   4
#define T_SEQ   2048
#define CDIM    1024
#define NHEAD   16
#define HD      64
#define MROWS   (BATCH * T_SEQ)  // 8192

// ---------------------------------------------------------------------------
// Scratch (allocation-free rule: __device__ globals)
// ---------------------------------------------------------------------------
__device__ __nv_bfloat16 g_xh[(size_t)MROWS * CDIM];
__device__ __nv_bfloat16 g_xl[(size_t)MROWS * CDIM];
__device__ __nv_bfloat16 g_qkvh[(size_t)MROWS * 3 * CDIM];
__device__ __nv_bfloat16 g_qkvl[(size_t)MROWS * 3 * CDIM];
__device__ __nv_bfloat16 g_yh[(size_t)MROWS * CDIM];
__device__ __nv_bfloat16 g_yl[(size_t)MROWS * CDIM];
__device__ __nv_bfloat16 g_wah[(size_t)3 * CDIM * CDIM];   // W_attn^T hi [3072][1024]
__device__ __nv_bfloat16 g_wal[(size_t)3 * CDIM * CDIM];
__device__ __nv_bfloat16 g_wph[(size_t)CDIM * CDIM];
__device__ __nv_bfloat16 g_wpl[(size_t)CDIM * CDIM];

// ---------------------------------------------------------------------------
// PTX helpers (sm_103-safe set only: cp.async / ldmatrix / mma.sync)
// ---------------------------------------------------------------------------
__device__ __forceinline__ void cp16(void* dst, const void* src) {
    uint32_t d = (uint32_t)__cvta_generic_to_shared(dst);
    asm volatile("cp.async.cg.shared.global [%0], [%1], 16;\n" :: "r"(d), "l"(src));
}
__device__ __forceinline__ void cp16r(uint32_t d, const void* src) {
    asm volatile("cp.async.cg.shared.global [%0], [%1], 16;\n" :: "r"(d), "l"(src));
}
__device__ __forceinline__ void cp_commit() {
    asm volatile("cp.async.commit_group;\n" ::: "memory");
}
template <int N> __device__ __forceinline__ void cp_wait() {
    asm volatile("cp.async.wait_group %0;\n" :: "n"(N) : "memory");
}
__device__ __forceinline__ void ldm_x4(uint32_t* r, const void* p) {
    uint32_t a = (uint32_t)__cvta_generic_to_shared(p);
    asm volatile("ldmatrix.sync.aligned.m8n8.x4.shared.b16 {%0,%1,%2,%3},[%4];\n"
                 : "=r"(r[0]), "=r"(r[1]), "=r"(r[2]), "=r"(r[3]) : "r"(a));
}
__device__ __forceinline__ void ldm_x2(uint32_t* r, const void* p) {
    uint32_t a = (uint32_t)__cvta_generic_to_shared(p);
    asm volatile("ldmatrix.sync.aligned.m8n8.x2.shared.b16 {%0,%1},[%2];\n"
                 : "=r"(r[0]), "=r"(r[1]) : "r"(a));
}
__device__ __forceinline__ void ldm_x2t(uint32_t* r, const void* p) {
    uint32_t a = (uint32_t)__cvta_generic_to_shared(p);
    asm volatile("ldmatrix.sync.aligned.m8n8.x2.trans.shared.b16 {%0,%1},[%2];\n"
                 : "=r"(r[0]), "=r"(r[1]) : "r"(a));
}
// raw-address variants (caller supplies shared-window u32 address)
__device__ __forceinline__ void ldm_x4r(uint32_t* r, uint32_t a) {
    asm volatile("ldmatrix.sync.aligned.m8n8.x4.shared.b16 {%0,%1,%2,%3},[%4];\n"
                 : "=r"(r[0]), "=r"(r[1]), "=r"(r[2]), "=r"(r[3]) : "r"(a));
}
__device__ __forceinline__ void mma_bf16(float* c, const uint32_t* a, const uint32_t* b) {
    asm volatile(
        "mma.sync.aligned.m16n8k16.row.col.f32.bf16.bf16.f32 "
        "{%0,%1,%2,%3},{%4,%5,%6,%7},{%8,%9},{%0,%1,%2,%3};\n"
        : "+f"(c[0]), "+f"(c[1]), "+f"(c[2]), "+f"(c[3])
        : "r"(a[0]), "r"(a[1]), "r"(a[2]), "r"(a[3]), "r"(b[0]), "r"(b[1]));
}
__device__ __forceinline__ void splitpack2(float a, float b, uint32_t& hi, uint32_t& lo) {
    __nv_bfloat16 ha = __float2bfloat16_rn(a);
    __nv_bfloat16 hb = __float2bfloat16_rn(b);
    __nv_bfloat16 la = __float2bfloat16_rn(a - __bfloat162float(ha));
    __nv_bfloat16 lb = __float2bfloat16_rn(b - __bfloat162float(hb));
    hi = (uint32_t)(*(uint16_t*)&ha) | ((uint32_t)(*(uint16_t*)&hb) << 16);
    lo = (uint32_t)(*(uint16_t*)&la) | ((uint32_t)(*(uint16_t*)&lb) << 16);
}

// ---------------------------------------------------------------------------
// Split conversion: fp32 -> hi + lo bf16
// ---------------------------------------------------------------------------
__global__ __launch_bounds__(256)
void split_kernel(const float* __restrict__ in, __nv_bfloat16* __restrict__ hi,
                  __nv_bfloat16* __restrict__ lo, int n4)
{
    int i = blockIdx.x * blockDim.x + threadIdx.x;
    if (i >= n4) return;
    float4 v = ((const float4*)in)[i];
    __nv_bfloat16 h[4], l[4];
    float vv[4] = {v.x, v.y, v.z, v.w};
    #pragma unroll
    for (int j = 0; j < 4; ++j) {
        h[j] = __float2bfloat16_rn(vv[j]);
        l[j] = __float2bfloat16_rn(vv[j] - __bfloat162float(h[j]));
    }
    ((uint2*)hi)[i] = *(uint2*)h;
    ((uint2*)lo)[i] = *(uint2*)l;
}

// ---------------------------------------------------------------------------
// Split + transpose: W [K][N] fp32 -> hiT, loT [N][K] bf16
// ---------------------------------------------------------------------------
__global__ __launch_bounds__(256)
void split_transpose_kernel(const float* __restrict__ W,
                            __nv_bfloat16* __restrict__ hiT,
                            __nv_bfloat16* __restrict__ loT, int K, int N)
{
    __shared__ float t[32][33];
    int n0 = blockIdx.x * 32;
    int k0 = blockIdx.y * 32;
    int tx = threadIdx.x, ty = threadIdx.y;   // 32 x 8
    #pragma unroll
    for (int r = 0; r < 32; r += 8)
        t[ty + r][tx] = W[(size_t)(k0 + ty + r) * N + n0 + tx];
    __syncthreads();
    #pragma unroll
    for (int r = 0; r < 32; r += 8) {
        float v = t[tx][ty + r];
        __nv_bfloat16 h = __float2bfloat16_rn(v);
        __nv_bfloat16 l = __float2bfloat16_rn(v - __bfloat162float(h));
        size_t o = (size_t)(n0 + ty + r) * K + k0 + tx;
        hiT[o] = h;
        loT[o] = l;
    }
}

// ---------------------------------------------------------------------------
// Split-bf16 mma.sync GEMM (3-term hh+hl+lh), 3-stage cp.async pipeline,
// SW128-swizzled tiles. B fragments loaded via ldmatrix.x4 (2 n-tiles per
// call); half-1's B frags prefetched during half-0's MMA block; cp.async
// prefetch slices interleaved into the MMA stream.
// Tile 128x128x32, 256 threads (8 warps, 2m x 4n), warp tile 64x32, 2 CTAs/SM.
// ---------------------------------------------------------------------------
#define GBM 128
#define GBN 128
#define GBK 32
#define TKB 32768                      // stage bytes (16KB A + 16KB B)
#define NSTAGE 3
#define GEMM_SMEM_BYTES (NSTAGE * TKB) // 98304 B

__global__ __launch_bounds__(256, 2)
void gemm_split_bf16(const __nv_bfloat16* __restrict__ Ah_g,
                     const __nv_bfloat16* __restrict__ Al_g,
                     const __nv_bfloat16* __restrict__ Bh_g,
                     const __nv_bfloat16* __restrict__ Bl_g,
                     const float* __restrict__ bias,
                     float* __restrict__ Cf,
                     __nv_bfloat16* __restrict__ Chi,
                     __nv_bfloat16* __restrict__ Clo,
                     int M, int N, int K)
{
    extern __shared__ char smem[];
    const uint32_t smem32 = (uint32_t)__cvta_generic_to_shared(smem);
    const int tid  = threadIdx.x;
    const int bm   = blockIdx.y * GBM;
    const int bn   = blockIdx.x * GBN;
    const int warp = tid >> 5, lane = tid & 31;
    const int wm   = (warp & 1) * 64;
    const int wn   = (warp >> 1) * 32;

    float acc[4][4][4];
    #pragma unroll
    for (int i = 0; i < 4; ++i)
        #pragma unroll
        for (int j = 0; j < 4; ++j)
            #pragma unroll
            for (int r = 0; r < 4; ++r) acc[i][j][r] = 0.f;

    // One slice of a stage load: p in 0..3. p<2 -> A rows, p>=2 -> B rows.
    auto load_part = [&](int s, int k0, int p) {
        uint32_t st = smem32 + s * TKB;
        if (p < 2) {
            int c = tid + p * 256;              // 0..511
            int row = c >> 2, cc = c & 3;
            size_t g = (size_t)(bm + row) * K + k0 + cc * 8;
            uint32_t d = st + row * 128 + ((cc ^ (row & 7)) * 16);
            cp16r(d,      Ah_g + g);
            cp16r(d ^ 64, Al_g + g);
        } else {
            int c = tid + (p - 2) * 256;
            int row = c >> 2, cc = c & 3;
            size_t g = (size_t)(bn + row) * K + k0 + cc * 8;
            uint32_t d = st + 16384 + row * 128 + ((cc ^ (row & 7)) * 16);
            cp16r(d,      Bh_g + g);
            cp16r(d ^ 64, Bl_g + g);
        }
    };

    const int niter = K / GBK;
    #pragma unroll
    for (int p = 0; p < 4; ++p) load_part(0, 0, p);
    cp_commit();
    #pragma unroll
    for (int p = 0; p < 4; ++p) load_part(1, GBK, p);
    cp_commit();

    // A address bases (hoisted; per-chunk adds stage base).
    const int arow0 = wm + (lane & 15);
    const int ac0   = lane >> 4;          // 0/1  (k-slice within half for A)
    // B x4 per-lane address: pair p covers n-tiles 2p,2p+1.
    //   matrix group g = lane>>3:  g&2 -> +8 rows (second n-tile of pair)
    //   g&1 -> k-slice (chunk +1)
    const int brow_x4 = wn + ((lane >> 4) & 1) * 8 + (lane & 7);
    const int bks     = (lane >> 3) & 1;

    int sc = 0, sn = 2;   // compute stage, prefetch-target stage (mod 3)
    for (int it = 0; it < niter; ++it) {
        if (it + 1 < niter) cp_wait<1>(); else cp_wait<0>();
        __syncthreads();

        const uint32_t aab = smem32 + sc * TKB;
        uint32_t aA[4];
        #pragma unroll
        for (int mt = 0; mt < 4; ++mt) {
            int row = arow0 + mt * 16;
            aA[mt] = aab + row * 128 + ((ac0 ^ (row & 7)) * 16);
        }
        // B x4 addresses, pair0/pair1, half0 hi (chunk = bks)
        const uint32_t bB0 = aab + 16384 + brow_x4 * 128 + ((bks ^ (brow_x4 & 7)) * 16);
        const uint32_t bB1 = bB0 + 2048;   // +16 rows

        const bool pf  = (it + 2 < niter);
        const int  nk0 = (it + 2) * GBK;

        // ---- load B half0 (hi+lo, both pairs) ----
        uint32_t b0h0[4], b0h1[4], b0l0[4], b0l1[4];
        ldm_x4r(b0h0, bB0);      ldm_x4r(b0h1, bB1);
        ldm_x4r(b0l0, bB0 ^ 64); ldm_x4r(b0l1, bB1 ^ 64);

        uint32_t b1h0[4], b1h1[4], b1l0[4], b1l1[4];   // half1 prefetch targets

        // ================= half 0 =================
        // hi-A block (hh + hl); prefetch half1 B frags between MMA groups
        #pragma unroll
        for (int mt = 0; mt < 4; ++mt) {
            uint32_t a[4];
            ldm_x4r(a, aA[mt]);
            if (mt == 0) ldm_x4r(b1h0, bB0 ^ 32);
            if (mt == 1) ldm_x4r(b1h1, bB1 ^ 32);
            if (mt == 2) ldm_x4r(b1l0, bB0 ^ 32 ^ 64);
            if (mt == 3) ldm_x4r(b1l1, bB1 ^ 32 ^ 64);
            mma_bf16(acc[mt][0], a, &b0h0[0]);
            mma_bf16(acc[mt][1], a, &b0h0[2]);
            mma_bf16(acc[mt][2], a, &b0h1[0]);
            mma_bf16(acc[mt][3], a, &b0h1[2]);
            if (pf && mt == 1) load_part(sn, nk0, 0);
            mma_bf16(acc[mt][0], a, &b0l0[0]);
            mma_bf16(acc[mt][1], a, &b0l0[2]);
            mma_bf16(acc[mt][2], a, &b0l1[0]);
            mma_bf16(acc[mt][3], a, &b0l1[2]);
        }
        // lo-A block (lh)
        #pragma unroll
        for (int mt = 0; mt < 4; ++mt) {
            uint32_t a[4];
            ldm_x4r(a, aA[mt] ^ 64);
            if (pf && mt == 1) load_part(sn, nk0, 1);
            mma_bf16(acc[mt][0], a, &b0h0[0]);
            mma_bf16(acc[mt][1], a, &b0h0[2]);
            mma_bf16(acc[mt][2], a, &b0h1[0]);
            mma_bf16(acc[mt][3], a, &b0h1[2]);
        }

        // ================= half 1 ================= (B frags already resident)
        #pragma unroll
        for (int mt = 0; mt < 4; ++mt) {
            uint32_t a[4];
            ldm_x4r(a, aA[mt] ^ 32);
            mma_bf16(acc[mt][0], a, &b1h0[0]);
            mma_bf16(acc[mt][1], a, &b1h0[2]);
            mma_bf16(acc[mt][2], a, &b1h1[0]);
            mma_bf16(acc[mt][3], a, &b1h1[2]);
            if (pf && mt == 1) load_part(sn, nk0, 2);
            mma_bf16(acc[mt][0], a, &b1l0[0]);
            mma_bf16(acc[mt][1], a, &b1l0[2]);
            mma_bf16(acc[mt][2], a, &b1l1[0]);
            mma_bf16(acc[mt][3], a, &b1l1[2]);
        }
        #pragma unroll
        for (int mt = 0; mt < 4; ++mt) {
            uint32_t a[4];
            ldm_x4r(a, aA[mt] ^ 32 ^ 64);
            if (pf && mt == 1) load_part(sn, nk0, 3);
            mma_bf16(acc[mt][0], a, &b1h0[0]);
            mma_bf16(acc[mt][1], a, &b1h0[2]);
            mma_bf16(acc[mt][2], a, &b1h1[0]);
            mma_bf16(acc[mt][3], a, &b1h1[2]);
        }

        if (pf) cp_commit();
        sc = (sc + 1 == NSTAGE) ? 0 : sc + 1;
        sn = (sn + 1 == NSTAGE) ? 0 : sn + 1;
    }

    // Epilogue: bias + store
    #pragma unroll
    for (int mt = 0; mt < 4; ++mt) {
        int r0 = bm + wm + mt * 16 + (lane >> 2);
        #pragma unroll
        for (int nt = 0; nt < 4; ++nt) {
            int cc = bn + wn + nt * 8 + (lane & 3) * 2;
            float b0 = bias[cc], b1 = bias[cc + 1];
            float v0 = acc[mt][nt][0] + b0, v1 = acc[mt][nt][1] + b1;
            float v2 = acc[mt][nt][2] + b0, v3 = acc[mt][nt][3] + b1;
            if (Cf) {
                *(float2*)(Cf + (size_t)r0 * N + cc)       = make_float2(v0, v1);
                *(float2*)(Cf + (size_t)(r0 + 8) * N + cc) = make_float2(v2, v3);
            } else {
                uint32_t h01, l01, h23, l23;
                splitpack2(v0, v1, h01, l01);
                splitpack2(v2, v3, h23, l23);
                *(uint32_t*)(Chi + (size_t)r0 * N + cc)       = h01;
                *(uint32_t*)(Clo + (size_t)r0 * N + cc)       = l01;
                *(uint32_t*)(Chi + (size_t)(r0 + 8) * N + cc) = h23;
                *(uint32_t*)(Clo + (size_t)(r0 + 8) * N + cc) = l23;
            }
        }
    }
}

// ---------------------------------------------------------------------------
// Tensor-core causal flash attention, split-bf16, BQ=128 (8 warps, 256 thr),
// 2 CTAs/SM. Row-sum shuffle reduction deferred until after PV MMAs.
// (unchanged from R11 passing version)
// ---------------------------------------------------------------------------
#define AROW  72
#define QTILE (128 * AROW)
#define KTILE (64 * AROW)
#define ASTG  (4 * KTILE)
#define FLASH_SMEM_BYTES ((2 * QTILE + 2 * ASTG) * 2)   // 110592 B

__global__ __launch_bounds__(256, 2)
void flash_attn_tc(const __nv_bfloat16* __restrict__ qkvh,
                   const __nv_bfloat16* __restrict__ qkvl,
                   __nv_bfloat16* __restrict__ yh,
                   __nv_bfloat16* __restrict__ yl)
{
    extern __shared__ __nv_bfloat16 sm[];
    __nv_bfloat16* Qh = sm;
    __nv_bfloat16* Ql = sm + QTILE;
    __nv_bfloat16* KV = sm + 2 * QTILE;

    const int qb = gridDim.x - 1 - blockIdx.x;
    const int h  = blockIdx.y;
    const int b  = blockIdx.z;
    const int q0 = qb * 128;
    const int tid = threadIdx.x, warp = tid >> 5, lane = tid & 31;

    const size_t rstride = (size_t)3 * CDIM;
    const size_t base = (size_t)b * T_SEQ * rstride + (size_t)h * HD;

    for (int i = tid; i < 1024; i += 256) {
        int r = i >> 3, ch = i & 7;
        size_t g = base + (size_t)(q0 + r) * rstride + ch * 8;
        cp16(Qh + r * AROW + ch * 8, qkvh + g);
        cp16(Ql + r * AROW + ch * 8, qkvl + g);
    }
    cp_commit();

    auto load_kv = [&](int s, int k0) {
        __nv_bfloat16* Kh = KV + s * ASTG;
        __nv_bfloat16* Kl = Kh + KTILE;
        __nv_bfloat16* Vh = Kl + KTILE;
        __nv_bfloat16* Vl = Vh + KTILE;
        for (int i = tid; i < 512; i += 256) {
            int r = i >> 3, ch = i & 7;
            size_t gk = base + CDIM + (size_t)(k0 + r) * rstride + ch * 8;
            size_t gv = gk + CDIM;
            cp16(Kh + r * AROW + ch * 8, qkvh + gk);
            cp16(Kl + r * AROW + ch * 8, qkvl + gk);
            cp16(Vh + r * AROW + ch * 8, qkvh + gv);
            cp16(Vl + r * AROW + ch * 8, qkvl + gv);
        }
    };
    load_kv(0, 0);
    cp_commit();

    float o[8][4];
    #pragma unroll
    for (int nb = 0; nb < 8; ++nb)
        #pragma unroll
        for (int r = 0; r < 4; ++r) o[nb][r] = 0.f;
    float m0 = -1e30f, m1 = -1e30f, l0 = 0.f, l1 = 0.f;

    const float SC = 0.125f * 1.4426950408889634f;
    const int rin   = lane >> 2;
    const int qrow0 = q0 + warp * 16 + rin;
    const int qrow1 = qrow0 + 8;
    const int cbase = 2 * (lane & 3);

    const int nkt = 2 * qb + 2;
    for (int kt = 0; kt < nkt; ++kt) {
        cp_wait<0>();
        __syncthreads();
        if (kt + 1 < nkt) { load_kv((kt + 1) & 1, (kt + 1) * 64); cp_commit(); }

        const __nv_bfloat16* Kh = KV + (kt & 1) * ASTG;
        const __nv_bfloat16* Kl = Kh + KTILE;
        const __nv_bfloat16* Vh = Kl + KTILE;
        const __nv_bfloat16* Vl = Vh + KTILE;

        float s[8][4];
        #pragma unroll
        for (int nb = 0; nb < 8; ++nb)
            #pragma unroll
            for (int r = 0; r < 4; ++r) s[nb][r] = 0.f;

        #pragma unroll
        for (int ks = 0; ks < 4; ++ks) {
            const int aoff = (warp * 16 + (lane & 15)) * AROW + ks * 16 + (lane >> 4) * 8;
            uint32_t ah[4], al[4];
            ldm_x4(ah, Qh + aoff);
            ldm_x4(al, Ql + aoff);
            #pragma unroll
            for (int nb = 0; nb < 8; ++nb) {
                const int boff = (nb * 8 + (lane & 7)) * AROW + ks * 16 + ((lane >> 3) & 1) * 8;
                uint32_t bh[2], bl[2];
                ldm_x2(bh, Kh + boff);
                ldm_x2(bl, Kl + boff);
                mma_bf16(s[nb], ah, bh);
                mma_bf16(s[nb], ah, bl);
                mma_bf16(s[nb], al, bh);
            }
        }

        const int k0 = kt * 64;
        if (kt >= 2 * qb) {
            #pragma unroll
            for (int nb = 0; nb < 8; ++nb) {
                int c0 = k0 + nb * 8 + cbase;
                s[nb][0] = (c0     <= qrow0) ? s[nb][0] * SC : -1e30f;
                s[nb][1] = (c0 + 1 <= qrow0) ? s[nb][1] * SC : -1e30f;
                s[nb][2] = (c0     <= qrow1) ? s[nb][2] * SC : -1e30f;
                s[nb][3] = (c0 + 1 <= qrow1) ? s[nb][3] * SC : -1e30f;
            }
        } else {
            #pragma unroll
            for (int nb = 0; nb < 8; ++nb)
                #pragma unroll
                for (int r = 0; r < 4; ++r) s[nb][r] *= SC;
        }

        float mx0 = -1e30f, mx1 = -1e30f;
        #pragma unroll
        for (int nb = 0; nb < 8; ++nb) {
            mx0 = fmaxf(mx0, fmaxf(s[nb][0], s[nb][1]));
            mx1 = fmaxf(mx1, fmaxf(s[nb][2], s[nb][3]));
        }
        mx0 = fmaxf(mx0, __shfl_xor_sync(0xffffffffu, mx0, 1));
        mx0 = fmaxf(mx0, __shfl_xor_sync(0xffffffffu, mx0, 2));
        mx1 = fmaxf(mx1, __shfl_xor_sync(0xffffffffu, mx1, 1));
        mx1 = fmaxf(mx1, __shfl_xor_sync(0xffffffffu, mx1, 2));

        float nm0 = fmaxf(m0, mx0), nm1 = fmaxf(m1, mx1);
        float sc0 = exp2f(m0 - nm0), sc1 = exp2f(m1 - nm1);
        m0 = nm0; m1 = nm1;

        float rs0 = 0.f, rs1 = 0.f;
        #pragma unroll
        for (int nb = 0; nb < 8; ++nb) {
            s[nb][0] = exp2f(s[nb][0] - nm0);
            s[nb][1] = exp2f(s[nb][1] - nm0);
            s[nb][2] = exp2f(s[nb][2] - nm1);
            s[nb][3] = exp2f(s[nb][3] - nm1);
            rs0 += s[nb][0] + s[nb][1];
            rs1 += s[nb][2] + s[nb][3];
        }

        #pragma unroll
        for (int nb = 0; nb < 8; ++nb) {
            o[nb][0] *= sc0; o[nb][1] *= sc0;
            o[nb][2] *= sc1; o[nb][3] *= sc1;
        }

        #pragma unroll
        for (int t = 0; t < 4; ++t) {
            uint32_t ph[4], pl[4];
            splitpack2(s[2*t  ][0], s[2*t  ][1], ph[0], pl[0]);
            splitpack2(s[2*t  ][2], s[2*t  ][3], ph[1], pl[1]);
            splitpack2(s[2*t+1][0], s[2*t+1][1], ph[2], pl[2]);
            splitpack2(s[2*t+1][2], s[2*t+1][3], ph[3], pl[3]);
            const int voff = (t * 16 + (lane & 15)) * AROW;
            #pragma unroll
            for (int nb = 0; nb < 8; ++nb) {
                uint32_t bh[2], bl[2];
                ldm_x2t(bh, Vh + voff + nb * 8);
                ldm_x2t(bl, Vl + voff + nb * 8);
                mma_bf16(o[nb], ph, bh);
                mma_bf16(o[nb], ph, bl);
                mma_bf16(o[nb], pl, bh);
            }
        }

        rs0 += __shfl_xor_sync(0xffffffffu, rs0, 1);
        rs0 += __shfl_xor_sync(0xffffffffu, rs0, 2);
        rs1 += __shfl_xor_sync(0xffffffffu, rs1, 1);
        rs1 += __shfl_xor_sync(0xffffffffu, rs1, 2);
        l0 = l0 * sc0 + rs0;
        l1 = l1 * sc1 + rs1;
    }

    float inv0 = 1.f / l0, inv1 = 1.f / l1;
    const size_t row0 = (size_t)b * T_SEQ + qrow0;
    const size_t row1 = (size_t)b * T_SEQ + qrow1;
    #pragma unroll
    for (int nb = 0; nb < 8; ++nb) {
        int cc = h * HD + nb * 8 + cbase;
        uint32_t h01, l01, h23, l23;
        splitpack2(o[nb][0] * inv0, o[nb][1] * inv0, h01, l01);
        splitpack2(o[nb][2] * inv1, o[nb][3] * inv1, h23, l23);
        *(uint32_t*)(yh + row0 * CDIM + cc) = h01;
        *(uint32_t*)(yl + row0 * CDIM + cc) = l01;
        *(uint32_t*)(yh + row1 * CDIM + cc) = h23;
        *(uint32_t*)(yl + row1 * CDIM + cc) = l23;
    }
}

// ---------------------------------------------------------------------------
// kernel_launch
// ---------------------------------------------------------------------------
extern "C" void kernel_launch(void* const* d_in, const int* in_sizes, int n_in,
                              void* d_out, int out_size)
{
    (void)in_sizes; (void)n_in; (void)out_size;
    const float* x      = (const float*)d_in[0];
    const float* W_attn = (const float*)d_in[1];
    const float* b_attn = (const float*)d_in[2];
    const float* W_proj = (const float*)d_in[3];
    const float* b_proj = (const float*)d_in[4];
    float* out = (float*)d_out;

    __nv_bfloat16 *xh, *xl, *qkvh, *qkvl, *yh, *yl, *wah, *wal, *wph, *wpl;
    cudaGetSymbolAddress((void**)&xh,   g_xh);
    cudaGetSymbolAddress((void**)&xl,   g_xl);
    cudaGetSymbolAddress((void**)&qkvh, g_qkvh);
    cudaGetSymbolAddress((void**)&qkvl, g_qkvl);
    cudaGetSymbolAddress((void**)&yh,   g_yh);
    cudaGetSymbolAddress((void**)&yl,   g_yl);
    cudaGetSymbolAddress((void**)&wah,  g_wah);
    cudaGetSymbolAddress((void**)&wal,  g_wal);
    cudaGetSymbolAddress((void**)&wph,  g_wph);
    cudaGetSymbolAddress((void**)&wpl,  g_wpl);

    cudaFuncSetAttribute(gemm_split_bf16, cudaFuncAttributeMaxDynamicSharedMemorySize,
                         GEMM_SMEM_BYTES);
    cudaFuncSetAttribute(flash_attn_tc, cudaFuncAttributeMaxDynamicSharedMemorySize,
                         FLASH_SMEM_BYTES);

    // 1) split x
    {
        int n4 = MROWS * CDIM / 4;
        split_kernel<<<(n4 + 255) / 256, 256>>>(x, xh, xl, n4);
    }
    // 2) split + transpose weights
    {
        dim3 blk(32, 8);
        split_transpose_kernel<<<dim3(3 * CDIM / 32, CDIM / 32), blk>>>(W_attn, wah, wal, CDIM, 3 * CDIM);
        split_transpose_kernel<<<dim3(CDIM / 32, CDIM / 32), blk>>>(W_proj, wph, wpl, CDIM, CDIM);
    }
    // 3) qkv(hi/lo) = split(x @ W_attn + b_attn)   [8192, 3072]
    {
        dim3 grid(3 * CDIM / GBN, MROWS / GBM);   // (24, 64)
        gemm_split_bf16<<<grid, 256, GEMM_SMEM_BYTES>>>(xh, xl, wah, wal, b_attn,
                                                        nullptr, qkvh, qkvl,
                                                        MROWS, 3 * CDIM, CDIM);
    }
    // 4) tensor-core flash attention -> yh/yl  (BQ=128)
    {
        dim3 grid(T_SEQ / 128, NHEAD, BATCH);
        flash_attn_tc<<<grid, 256, FLASH_SMEM_BYTES>>>(qkvh, qkvl, yh, yl);
    }
    // 5) out = y @ W_proj + b_proj   [8192, 1024] fp32
    {
        dim3 grid(CDIM / GBN, MROWS / GBM);       // (8, 64)
        gemm_split_bf16<<<grid, 256, GEMM_SMEM_BYTES>>>(yh, yl, wph, wpl, b_proj,
                                                        out, nullptr, nullptr,
                                                        MROWS, CDIM, CDIM);
    }
}

// round 14
// speedup vs baseline: 1.0508x; 1.0508x over previous
#include <cuda_runtime.h>
#include <cuda_bf16.h>
#include <math.h>
#include <stdint.h>

// Problem constants
#define BATCH   4
#define T_SEQ   2048
#define CDIM    1024
#define NHEAD   16
#define HD      64
#define MROWS   (BATCH * T_SEQ)  // 8192

// ---------------------------------------------------------------------------
// Scratch (allocation-free rule: __device__ globals)
// ---------------------------------------------------------------------------
__device__ __nv_bfloat16 g_xh[(size_t)MROWS * CDIM];
__device__ __nv_bfloat16 g_xl[(size_t)MROWS * CDIM];
__device__ __nv_bfloat16 g_qkvh[(size_t)MROWS * 3 * CDIM];
__device__ __nv_bfloat16 g_qkvl[(size_t)MROWS * 3 * CDIM];
__device__ __nv_bfloat16 g_yh[(size_t)MROWS * CDIM];
__device__ __nv_bfloat16 g_yl[(size_t)MROWS * CDIM];
__device__ __nv_bfloat16 g_wah[(size_t)3 * CDIM * CDIM];   // W_attn^T hi [3072][1024]
__device__ __nv_bfloat16 g_wal[(size_t)3 * CDIM * CDIM];
__device__ __nv_bfloat16 g_wph[(size_t)CDIM * CDIM];
__device__ __nv_bfloat16 g_wpl[(size_t)CDIM * CDIM];

// ---------------------------------------------------------------------------
// PTX helpers (sm_103-safe set only: cp.async / ldmatrix / mma.sync)
// ---------------------------------------------------------------------------
__device__ __forceinline__ void cp16(void* dst, const void* src) {
    uint32_t d = (uint32_t)__cvta_generic_to_shared(dst);
    asm volatile("cp.async.cg.shared.global [%0], [%1], 16;\n" :: "r"(d), "l"(src));
}
__device__ __forceinline__ void cp16r(uint32_t d, const void* src) {
    asm volatile("cp.async.cg.shared.global [%0], [%1], 16;\n" :: "r"(d), "l"(src));
}
__device__ __forceinline__ void cp_commit() {
    asm volatile("cp.async.commit_group;\n" ::: "memory");
}
template <int N> __device__ __forceinline__ void cp_wait() {
    asm volatile("cp.async.wait_group %0;\n" :: "n"(N) : "memory");
}
__device__ __forceinline__ void ldm_x4(uint32_t* r, const void* p) {
    uint32_t a = (uint32_t)__cvta_generic_to_shared(p);
    asm volatile("ldmatrix.sync.aligned.m8n8.x4.shared.b16 {%0,%1,%2,%3},[%4];\n"
                 : "=r"(r[0]), "=r"(r[1]), "=r"(r[2]), "=r"(r[3]) : "r"(a));
}
__device__ __forceinline__ void ldm_x4t(uint32_t* r, const void* p) {
    uint32_t a = (uint32_t)__cvta_generic_to_shared(p);
    asm volatile("ldmatrix.sync.aligned.m8n8.x4.trans.shared.b16 {%0,%1,%2,%3},[%4];\n"
                 : "=r"(r[0]), "=r"(r[1]), "=r"(r[2]), "=r"(r[3]) : "r"(a));
}
// raw-address variants (caller supplies shared-window u32 address)
__device__ __forceinline__ void ldm_x4r(uint32_t* r, uint32_t a) {
    asm volatile("ldmatrix.sync.aligned.m8n8.x4.shared.b16 {%0,%1,%2,%3},[%4];\n"
                 : "=r"(r[0]), "=r"(r[1]), "=r"(r[2]), "=r"(r[3]) : "r"(a));
}
__device__ __forceinline__ void ldm_x2r(uint32_t* r, uint32_t a) {
    asm volatile("ldmatrix.sync.aligned.m8n8.x2.shared.b16 {%0,%1},[%2];\n"
                 : "=r"(r[0]), "=r"(r[1]) : "r"(a));
}
__device__ __forceinline__ void mma_bf16(float* c, const uint32_t* a, const uint32_t* b) {
    asm volatile(
        "mma.sync.aligned.m16n8k16.row.col.f32.bf16.bf16.f32 "
        "{%0,%1,%2,%3},{%4,%5,%6,%7},{%8,%9},{%0,%1,%2,%3};\n"
        : "+f"(c[0]), "+f"(c[1]), "+f"(c[2]), "+f"(c[3])
        : "r"(a[0]), "r"(a[1]), "r"(a[2]), "r"(a[3]), "r"(b[0]), "r"(b[1]));
}
__device__ __forceinline__ void splitpack2(float a, float b, uint32_t& hi, uint32_t& lo) {
    __nv_bfloat16 ha = __float2bfloat16_rn(a);
    __nv_bfloat16 hb = __float2bfloat16_rn(b);
    __nv_bfloat16 la = __float2bfloat16_rn(a - __bfloat162float(ha));
    __nv_bfloat16 lb = __float2bfloat16_rn(b - __bfloat162float(hb));
    hi = (uint32_t)(*(uint16_t*)&ha) | ((uint32_t)(*(uint16_t*)&hb) << 16);
    lo = (uint32_t)(*(uint16_t*)&la) | ((uint32_t)(*(uint16_t*)&lb) << 16);
}

// ---------------------------------------------------------------------------
// Split conversion: fp32 -> hi + lo bf16
// ---------------------------------------------------------------------------
__global__ __launch_bounds__(256)
void split_kernel(const float* __restrict__ in, __nv_bfloat16* __restrict__ hi,
                  __nv_bfloat16* __restrict__ lo, int n4)
{
    int i = blockIdx.x * blockDim.x + threadIdx.x;
    if (i >= n4) return;
    float4 v = ((const float4*)in)[i];
    __nv_bfloat16 h[4], l[4];
    float vv[4] = {v.x, v.y, v.z, v.w};
    #pragma unroll
    for (int j = 0; j < 4; ++j) {
        h[j] = __float2bfloat16_rn(vv[j]);
        l[j] = __float2bfloat16_rn(vv[j] - __bfloat162float(h[j]));
    }
    ((uint2*)hi)[i] = *(uint2*)h;
    ((uint2*)lo)[i] = *(uint2*)l;
}

// ---------------------------------------------------------------------------
// Split + transpose: W [K][N] fp32 -> hiT, loT [N][K] bf16
// ---------------------------------------------------------------------------
__global__ __launch_bounds__(256)
void split_transpose_kernel(const float* __restrict__ W,
                            __nv_bfloat16* __restrict__ hiT,
                            __nv_bfloat16* __restrict__ loT, int K, int N)
{
    __shared__ float t[32][33];
    int n0 = blockIdx.x * 32;
    int k0 = blockIdx.y * 32;
    int tx = threadIdx.x, ty = threadIdx.y;   // 32 x 8
    #pragma unroll
    for (int r = 0; r < 32; r += 8)
        t[ty + r][tx] = W[(size_t)(k0 + ty + r) * N + n0 + tx];
    __syncthreads();
    #pragma unroll
    for (int r = 0; r < 32; r += 8) {
        float v = t[tx][ty + r];
        __nv_bfloat16 h = __float2bfloat16_rn(v);
        __nv_bfloat16 l = __float2bfloat16_rn(v - __bfloat162float(h));
        size_t o = (size_t)(n0 + ty + r) * K + k0 + tx;
        hiT[o] = h;
        loT[o] = l;
    }
}

// ---------------------------------------------------------------------------
// Split-bf16 mma.sync GEMM — R11 version verbatim (best measured: 370us).
// 3-term hh+hl+lh, 3-stage cp.async, SW128-swizzled tiles, hoisted addresses,
// A fragments consumed per-mt, prefetch interleaved into the MMA stream.
// Tile 128x128x32, 256 threads (8 warps, 2m x 4n), warp tile 64x32, 2 CTAs/SM.
// ---------------------------------------------------------------------------
#define GBM 128
#define GBN 128
#define GBK 32
#define TKB 32768                      // stage bytes (16KB A + 16KB B)
#define NSTAGE 3
#define GEMM_SMEM_BYTES (NSTAGE * TKB) // 98304 B

__global__ __launch_bounds__(256, 2)
void gemm_split_bf16(const __nv_bfloat16* __restrict__ Ah_g,
                     const __nv_bfloat16* __restrict__ Al_g,
                     const __nv_bfloat16* __restrict__ Bh_g,
                     const __nv_bfloat16* __restrict__ Bl_g,
                     const float* __restrict__ bias,
                     float* __restrict__ Cf,
                     __nv_bfloat16* __restrict__ Chi,
                     __nv_bfloat16* __restrict__ Clo,
                     int M, int N, int K)
{
    extern __shared__ char smem[];
    const uint32_t smem32 = (uint32_t)__cvta_generic_to_shared(smem);
    const int tid  = threadIdx.x;
    const int bm   = blockIdx.y * GBM;
    const int bn   = blockIdx.x * GBN;
    const int warp = tid >> 5, lane = tid & 31;
    const int wm   = (warp & 1) * 64;
    const int wn   = (warp >> 1) * 32;

    float acc[4][4][4];
    #pragma unroll
    for (int i = 0; i < 4; ++i)
        #pragma unroll
        for (int j = 0; j < 4; ++j)
            #pragma unroll
            for (int r = 0; r < 4; ++r) acc[i][j][r] = 0.f;

    auto load_part = [&](int s, int k0, int p) {
        uint32_t st = smem32 + s * TKB;
        if (p < 2) {
            int c = tid + p * 256;
            int row = c >> 2, cc = c & 3;
            size_t g = (size_t)(bm + row) * K + k0 + cc * 8;
            uint32_t d = st + row * 128 + ((cc ^ (row & 7)) * 16);
            cp16r(d,      Ah_g + g);
            cp16r(d ^ 64, Al_g + g);
        } else {
            int c = tid + (p - 2) * 256;
            int row = c >> 2, cc = c & 3;
            size_t g = (size_t)(bn + row) * K + k0 + cc * 8;
            uint32_t d = st + 16384 + row * 128 + ((cc ^ (row & 7)) * 16);
            cp16r(d,      Bh_g + g);
            cp16r(d ^ 64, Bl_g + g);
        }
    };

    const int niter = K / GBK;
    #pragma unroll
    for (int p = 0; p < 4; ++p) load_part(0, 0, p);
    cp_commit();
    #pragma unroll
    for (int p = 0; p < 4; ++p) load_part(1, GBK, p);
    cp_commit();

    const int arow0 = wm + (lane & 15);
    const int brow0 = wn + (lane & 7);
    const int ac0   = lane >> 4;
    const int bc0   = (lane >> 3) & 1;

    int sc = 0, sn = 2;
    for (int it = 0; it < niter; ++it) {
        if (it + 1 < niter) cp_wait<1>(); else cp_wait<0>();
        __syncthreads();

        uint32_t aab = smem32 + sc * TKB;
        uint32_t aA[4], bA[4];
        #pragma unroll
        for (int mt = 0; mt < 4; ++mt) {
            int row = arow0 + mt * 16;
            aA[mt] = aab + row * 128 + ((ac0 ^ (row & 7)) * 16);
        }
        #pragma unroll
        for (int nt = 0; nt < 4; ++nt) {
            int row = brow0 + nt * 8;
            bA[nt] = aab + 16384 + row * 128 + ((bc0 ^ (row & 7)) * 16);
        }

        const bool pf  = (it + 2 < niter);
        const int  nk0 = (it + 2) * GBK;

        #pragma unroll
        for (int half = 0; half < 2; ++half) {
            const uint32_t ko = half * 32;

            uint32_t bfh[4][2], bfl[4][2];
            #pragma unroll
            for (int nt = 0; nt < 4; ++nt) {
                ldm_x2r(bfh[nt], bA[nt] ^ ko);
                ldm_x2r(bfl[nt], bA[nt] ^ ko ^ 64);
            }
            #pragma unroll
            for (int mt = 0; mt < 4; ++mt) {
                uint32_t afh[4];
                ldm_x4r(afh, aA[mt] ^ ko);
                #pragma unroll
                for (int nt = 0; nt < 4; ++nt)
                    mma_bf16(acc[mt][nt], afh, bfh[nt]);
                if (pf && mt == 1) load_part(sn, nk0, half * 2);
                #pragma unroll
                for (int nt = 0; nt < 4; ++nt)
                    mma_bf16(acc[mt][nt], afh, bfl[nt]);
            }
            #pragma unroll
            for (int mt = 0; mt < 4; ++mt) {
                uint32_t afl[4];
                ldm_x4r(afl, aA[mt] ^ ko ^ 64);
                if (pf && mt == 1) load_part(sn, nk0, half * 2 + 1);
                #pragma unroll
                for (int nt = 0; nt < 4; ++nt)
                    mma_bf16(acc[mt][nt], afl, bfh[nt]);
            }
        }
        if (pf) cp_commit();
        sc = (sc + 1 == NSTAGE) ? 0 : sc + 1;
        sn = (sn + 1 == NSTAGE) ? 0 : sn + 1;
    }

    // Epilogue: bias + store
    #pragma unroll
    for (int mt = 0; mt < 4; ++mt) {
        int r0 = bm + wm + mt * 16 + (lane >> 2);
        #pragma unroll
        for (int nt = 0; nt < 4; ++nt) {
            int cc = bn + wn + nt * 8 + (lane & 3) * 2;
            float b0 = bias[cc], b1 = bias[cc + 1];
            float v0 = acc[mt][nt][0] + b0, v1 = acc[mt][nt][1] + b1;
            float v2 = acc[mt][nt][2] + b0, v3 = acc[mt][nt][3] + b1;
            if (Cf) {
                *(float2*)(Cf + (size_t)r0 * N + cc)       = make_float2(v0, v1);
                *(float2*)(Cf + (size_t)(r0 + 8) * N + cc) = make_float2(v2, v3);
            } else {
                uint32_t h01, l01, h23, l23;
                splitpack2(v0, v1, h01, l01);
                splitpack2(v2, v3, h23, l23);
                *(uint32_t*)(Chi + (size_t)r0 * N + cc)       = h01;
                *(uint32_t*)(Clo + (size_t)r0 * N + cc)       = l01;
                *(uint32_t*)(Chi + (size_t)(r0 + 8) * N + cc) = h23;
                *(uint32_t*)(Clo + (size_t)(r0 + 8) * N + cc) = l23;
            }
        }
    }
}

// ---------------------------------------------------------------------------
// Tensor-core causal flash attention, split-bf16, BQ=128 (8 warps, 256 thr),
// 2 CTAs/SM. K and V fragments via ldmatrix.x4 (two n-tiles per call) to
// halve the LDSM issue count (previous bottleneck).
// ---------------------------------------------------------------------------
#define AROW  72
#define QTILE (128 * AROW)
#define KTILE (64 * AROW)
#define ASTG  (4 * KTILE)
#define FLASH_SMEM_BYTES ((2 * QTILE + 2 * ASTG) * 2)   // 110592 B

__global__ __launch_bounds__(256, 2)
void flash_attn_tc(const __nv_bfloat16* __restrict__ qkvh,
                   const __nv_bfloat16* __restrict__ qkvl,
                   __nv_bfloat16* __restrict__ yh,
                   __nv_bfloat16* __restrict__ yl)
{
    extern __shared__ __nv_bfloat16 sm[];
    __nv_bfloat16* Qh = sm;
    __nv_bfloat16* Ql = sm + QTILE;
    __nv_bfloat16* KV = sm + 2 * QTILE;

    const int qb = gridDim.x - 1 - blockIdx.x;
    const int h  = blockIdx.y;
    const int b  = blockIdx.z;
    const int q0 = qb * 128;
    const int tid = threadIdx.x, warp = tid >> 5, lane = tid & 31;

    const size_t rstride = (size_t)3 * CDIM;
    const size_t base = (size_t)b * T_SEQ * rstride + (size_t)h * HD;

    for (int i = tid; i < 1024; i += 256) {
        int r = i >> 3, ch = i & 7;
        size_t g = base + (size_t)(q0 + r) * rstride + ch * 8;
        cp16(Qh + r * AROW + ch * 8, qkvh + g);
        cp16(Ql + r * AROW + ch * 8, qkvl + g);
    }
    cp_commit();

    auto load_kv = [&](int s, int k0) {
        __nv_bfloat16* Kh = KV + s * ASTG;
        __nv_bfloat16* Kl = Kh + KTILE;
        __nv_bfloat16* Vh = Kl + KTILE;
        __nv_bfloat16* Vl = Vh + KTILE;
        for (int i = tid; i < 512; i += 256) {
            int r = i >> 3, ch = i & 7;
            size_t gk = base + CDIM + (size_t)(k0 + r) * rstride + ch * 8;
            size_t gv = gk + CDIM;
            cp16(Kh + r * AROW + ch * 8, qkvh + gk);
            cp16(Kl + r * AROW + ch * 8, qkvl + gk);
            cp16(Vh + r * AROW + ch * 8, qkvh + gv);
            cp16(Vl + r * AROW + ch * 8, qkvl + gv);
        }
    };
    load_kv(0, 0);
    cp_commit();

    float o[8][4];
    #pragma unroll
    for (int nb = 0; nb < 8; ++nb)
        #pragma unroll
        for (int r = 0; r < 4; ++r) o[nb][r] = 0.f;
    float m0 = -1e30f, m1 = -1e30f, l0 = 0.f, l1 = 0.f;

    const float SC = 0.125f * 1.4426950408889634f;
    const int rin   = lane >> 2;
    const int qrow0 = q0 + warp * 16 + rin;
    const int qrow1 = qrow0 + 8;
    const int cbase = 2 * (lane & 3);

    // K x4 per-lane row/col: matrices 0,1 = n-tile 2*nbp (b-frag), 2,3 = 2*nbp+1
    const int krow_x4 = ((lane >> 4) & 1) * 8 + (lane & 7);   // + nbp*16
    const int kcol_x4 = ((lane >> 3) & 1) * 8;                // + ks*16
    // V x4t per-lane: lanes 0-15 rows of t-slice, lanes 16-31 same rows col+8
    const int vrow_x4 = lane & 15;                            // + t*16
    const int vcol_x4 = ((lane >> 4) & 1) * 8;                // + nbp*16

    const int nkt = 2 * qb + 2;
    for (int kt = 0; kt < nkt; ++kt) {
        cp_wait<0>();
        __syncthreads();
        if (kt + 1 < nkt) { load_kv((kt + 1) & 1, (kt + 1) * 64); cp_commit(); }

        const __nv_bfloat16* Kh = KV + (kt & 1) * ASTG;
        const __nv_bfloat16* Kl = Kh + KTILE;
        const __nv_bfloat16* Vh = Kl + KTILE;
        const __nv_bfloat16* Vl = Vh + KTILE;

        float s[8][4];
        #pragma unroll
        for (int nb = 0; nb < 8; ++nb)
            #pragma unroll
            for (int r = 0; r < 4; ++r) s[nb][r] = 0.f;

        // ---- S = Q K^T (3-term), K via x4 (2 n-tiles per call) ----
        #pragma unroll
        for (int ks = 0; ks < 4; ++ks) {
            const int aoff = (warp * 16 + (lane & 15)) * AROW + ks * 16 + (lane >> 4) * 8;
            uint32_t ah[4], al[4];
            ldm_x4(ah, Qh + aoff);
            ldm_x4(al, Ql + aoff);
            #pragma unroll
            for (int nbp = 0; nbp < 4; ++nbp) {
                const int koff = (nbp * 16 + krow_x4) * AROW + ks * 16 + kcol_x4;
                uint32_t kh[4], kl[4];
                ldm_x4(kh, Kh + koff);
                ldm_x4(kl, Kl + koff);
                mma_bf16(s[2*nbp  ], ah, &kh[0]);
                mma_bf16(s[2*nbp+1], ah, &kh[2]);
                mma_bf16(s[2*nbp  ], ah, &kl[0]);
                mma_bf16(s[2*nbp+1], ah, &kl[2]);
                mma_bf16(s[2*nbp  ], al, &kh[0]);
                mma_bf16(s[2*nbp+1], al, &kh[2]);
            }
        }

        const int k0 = kt * 64;
        if (kt >= 2 * qb) {
            #pragma unroll
            for (int nb = 0; nb < 8; ++nb) {
                int c0 = k0 + nb * 8 + cbase;
                s[nb][0] = (c0     <= qrow0) ? s[nb][0] * SC : -1e30f;
                s[nb][1] = (c0 + 1 <= qrow0) ? s[nb][1] * SC : -1e30f;
                s[nb][2] = (c0     <= qrow1) ? s[nb][2] * SC : -1e30f;
                s[nb][3] = (c0 + 1 <= qrow1) ? s[nb][3] * SC : -1e30f;
            }
        } else {
            #pragma unroll
            for (int nb = 0; nb < 8; ++nb)
                #pragma unroll
                for (int r = 0; r < 4; ++r) s[nb][r] *= SC;
        }

        float mx0 = -1e30f, mx1 = -1e30f;
        #pragma unroll
        for (int nb = 0; nb < 8; ++nb) {
            mx0 = fmaxf(mx0, fmaxf(s[nb][0], s[nb][1]));
            mx1 = fmaxf(mx1, fmaxf(s[nb][2], s[nb][3]));
        }
        mx0 = fmaxf(mx0, __shfl_xor_sync(0xffffffffu, mx0, 1));
        mx0 = fmaxf(mx0, __shfl_xor_sync(0xffffffffu, mx0, 2));
        mx1 = fmaxf(mx1, __shfl_xor_sync(0xffffffffu, mx1, 1));
        mx1 = fmaxf(mx1, __shfl_xor_sync(0xffffffffu, mx1, 2));

        float nm0 = fmaxf(m0, mx0), nm1 = fmaxf(m1, mx1);
        float sc0 = exp2f(m0 - nm0), sc1 = exp2f(m1 - nm1);
        m0 = nm0; m1 = nm1;

        float rs0 = 0.f, rs1 = 0.f;
        #pragma unroll
        for (int nb = 0; nb < 8; ++nb) {
            s[nb][0] = exp2f(s[nb][0] - nm0);
            s[nb][1] = exp2f(s[nb][1] - nm0);
            s[nb][2] = exp2f(s[nb][2] - nm1);
            s[nb][3] = exp2f(s[nb][3] - nm1);
            rs0 += s[nb][0] + s[nb][1];
            rs1 += s[nb][2] + s[nb][3];
        }

        #pragma unroll
        for (int nb = 0; nb < 8; ++nb) {
            o[nb][0] *= sc0; o[nb][1] *= sc0;
            o[nb][2] *= sc1; o[nb][3] *= sc1;
        }

        // ---- O += P V (3-term), V via x4.trans (2 n-tiles per call) ----
        #pragma unroll
        for (int t = 0; t < 4; ++t) {
            uint32_t ph[4], pl[4];
            splitpack2(s[2*t  ][0], s[2*t  ][1], ph[0], pl[0]);
            splitpack2(s[2*t  ][2], s[2*t  ][3], ph[1], pl[1]);
            splitpack2(s[2*t+1][0], s[2*t+1][1], ph[2], pl[2]);
            splitpack2(s[2*t+1][2], s[2*t+1][3], ph[3], pl[3]);
            const int vbase = (t * 16 + vrow_x4) * AROW;
            #pragma unroll
            for (int nbp = 0; nbp < 4; ++nbp) {
                const int voff = vbase + nbp * 16 + vcol_x4;
                uint32_t vh[4], vl[4];
                ldm_x4t(vh, Vh + voff);
                ldm_x4t(vl, Vl + voff);
                mma_bf16(o[2*nbp  ], ph, &vh[0]);
                mma_bf16(o[2*nbp+1], ph, &vh[2]);
                mma_bf16(o[2*nbp  ], ph, &vl[0]);
                mma_bf16(o[2*nbp+1], ph, &vl[2]);
                mma_bf16(o[2*nbp  ], pl, &vh[0]);
                mma_bf16(o[2*nbp+1], pl, &vh[2]);
            }
        }

        rs0 += __shfl_xor_sync(0xffffffffu, rs0, 1);
        rs0 += __shfl_xor_sync(0xffffffffu, rs0, 2);
        rs1 += __shfl_xor_sync(0xffffffffu, rs1, 1);
        rs1 += __shfl_xor_sync(0xffffffffu, rs1, 2);
        l0 = l0 * sc0 + rs0;
        l1 = l1 * sc1 + rs1;
    }

    float inv0 = 1.f / l0, inv1 = 1.f / l1;
    const size_t row0 = (size_t)b * T_SEQ + qrow0;
    const size_t row1 = (size_t)b * T_SEQ + qrow1;
    #pragma unroll
    for (int nb = 0; nb < 8; ++nb) {
        int cc = h * HD + nb * 8 + cbase;
        uint32_t h01, l01, h23, l23;
        splitpack2(o[nb][0] * inv0, o[nb][1] * inv0, h01, l01);
        splitpack2(o[nb][2] * inv1, o[nb][3] * inv1, h23, l23);
        *(uint32_t*)(yh + row0 * CDIM + cc) = h01;
        *(uint32_t*)(yl + row0 * CDIM + cc) = l01;
        *(uint32_t*)(yh + row1 * CDIM + cc) = h23;
        *(uint32_t*)(yl + row1 * CDIM + cc) = l23;
    }
}

// ---------------------------------------------------------------------------
// kernel_launch
// ---------------------------------------------------------------------------
extern "C" void kernel_launch(void* const* d_in, const int* in_sizes, int n_in,
                              void* d_out, int out_size)
{
    (void)in_sizes; (void)n_in; (void)out_size;
    const float* x      = (const float*)d_in[0];
    const float* W_attn = (const float*)d_in[1];
    const float* b_attn = (const float*)d_in[2];
    const float* W_proj = (const float*)d_in[3];
    const float* b_proj = (const float*)d_in[4];
    float* out = (float*)d_out;

    __nv_bfloat16 *xh, *xl, *qkvh, *qkvl, *yh, *yl, *wah, *wal, *wph, *wpl;
    cudaGetSymbolAddress((void**)&xh,   g_xh);
    cudaGetSymbolAddress((void**)&xl,   g_xl);
    cudaGetSymbolAddress((void**)&qkvh, g_qkvh);
    cudaGetSymbolAddress((void**)&qkvl, g_qkvl);
    cudaGetSymbolAddress((void**)&yh,   g_yh);
    cudaGetSymbolAddress((void**)&yl,   g_yl);
    cudaGetSymbolAddress((void**)&wah,  g_wah);
    cudaGetSymbolAddress((void**)&wal,  g_wal);
    cudaGetSymbolAddress((void**)&wph,  g_wph);
    cudaGetSymbolAddress((void**)&wpl,  g_wpl);

    cudaFuncSetAttribute(gemm_split_bf16, cudaFuncAttributeMaxDynamicSharedMemorySize,
                         GEMM_SMEM_BYTES);
    cudaFuncSetAttribute(flash_attn_tc, cudaFuncAttributeMaxDynamicSharedMemorySize,
                         FLASH_SMEM_BYTES);

    // 1) split x
    {
        int n4 = MROWS * CDIM / 4;
        split_kernel<<<(n4 + 255) / 256, 256>>>(x, xh, xl, n4);
    }
    // 2) split + transpose weights
    {
        dim3 blk(32, 8);
        split_transpose_kernel<<<dim3(3 * CDIM / 32, CDIM / 32), blk>>>(W_attn, wah, wal, CDIM, 3 * CDIM);
        split_transpose_kernel<<<dim3(CDIM / 32, CDIM / 32), blk>>>(W_proj, wph, wpl, CDIM, CDIM);
    }
    // 3) qkv(hi/lo) = split(x @ W_attn + b_attn)   [8192, 3072]
    {
        dim3 grid(3 * CDIM / GBN, MROWS / GBM);   // (24, 64)
        gemm_split_bf16<<<grid, 256, GEMM_SMEM_BYTES>>>(xh, xl, wah, wal, b_attn,
                                                        nullptr, qkvh, qkvl,
                                                        MROWS, 3 * CDIM, CDIM);
    }
    // 4) tensor-core flash attention -> yh/yl  (BQ=128)
    {
        dim3 grid(T_SEQ / 128, NHEAD, BATCH);
        flash_attn_tc<<<grid, 256, FLASH_SMEM_BYTES>>>(qkvh, qkvl, yh, yl);
    }
    // 5) out = y @ W_proj + b_proj   [8192, 1024] fp32
    {
        dim3 grid(CDIM / GBN, MROWS / GBM);       // (8, 64)
        gemm_split_bf16<<<grid, 256, GEMM_SMEM_BYTES>>>(yh, yl, wph, wpl, b_proj,
                                                        out, nullptr, nullptr,
                                                        MROWS, CDIM, CDIM);
    }
}

// round 15
// speedup vs baseline: 1.2458x; 1.1856x over previous
#include <cuda_runtime.h>
#include <cuda_bf16.h>
#include <cuda_fp16.h>
#include <math.h>
#include <stdint.h>

// Problem constants
#define BATCH   4
#define T_SEQ   2048
#define CDIM    1024
#define NHEAD   16
#define HD      64
#define MROWS   (BATCH * T_SEQ)  // 8192

// ---------------------------------------------------------------------------
// Scratch (allocation-free rule: __device__ globals)
// ---------------------------------------------------------------------------
__device__ __half g_xh[(size_t)MROWS * CDIM];               // fp16 splits (GEMM in)
__device__ __half g_xl[(size_t)MROWS * CDIM];
__device__ __nv_bfloat16 g_qkvh[(size_t)MROWS * 3 * CDIM];  // bf16 (attention in)
__device__ __nv_bfloat16 g_qkvl[(size_t)MROWS * 3 * CDIM];
__device__ __half g_yh[(size_t)MROWS * CDIM];               // fp16 (proj GEMM in)
__device__ __half g_yl[(size_t)MROWS * CDIM];
__device__ __half g_wah[(size_t)3 * CDIM * CDIM];           // W_attn^T fp16 [3072][1024]
__device__ __half g_wal[(size_t)3 * CDIM * CDIM];
__device__ __half g_wph[(size_t)CDIM * CDIM];
__device__ __half g_wpl[(size_t)CDIM * CDIM];

// ---------------------------------------------------------------------------
// PTX helpers (sm_103-safe set only: cp.async / ldmatrix / mma.sync)
// ---------------------------------------------------------------------------
__device__ __forceinline__ void cp16(void* dst, const void* src) {
    uint32_t d = (uint32_t)__cvta_generic_to_shared(dst);
    asm volatile("cp.async.cg.shared.global [%0], [%1], 16;\n" :: "r"(d), "l"(src));
}
__device__ __forceinline__ void cp16r(uint32_t d, const void* src) {
    asm volatile("cp.async.cg.shared.global [%0], [%1], 16;\n" :: "r"(d), "l"(src));
}
__device__ __forceinline__ void cp_commit() {
    asm volatile("cp.async.commit_group;\n" ::: "memory");
}
template <int N> __device__ __forceinline__ void cp_wait() {
    asm volatile("cp.async.wait_group %0;\n" :: "n"(N) : "memory");
}
__device__ __forceinline__ void ldm_x4(uint32_t* r, const void* p) {
    uint32_t a = (uint32_t)__cvta_generic_to_shared(p);
    asm volatile("ldmatrix.sync.aligned.m8n8.x4.shared.b16 {%0,%1,%2,%3},[%4];\n"
                 : "=r"(r[0]), "=r"(r[1]), "=r"(r[2]), "=r"(r[3]) : "r"(a));
}
__device__ __forceinline__ void ldm_x4t(uint32_t* r, const void* p) {
    uint32_t a = (uint32_t)__cvta_generic_to_shared(p);
    asm volatile("ldmatrix.sync.aligned.m8n8.x4.trans.shared.b16 {%0,%1,%2,%3},[%4];\n"
                 : "=r"(r[0]), "=r"(r[1]), "=r"(r[2]), "=r"(r[3]) : "r"(a));
}
__device__ __forceinline__ void ldm_x4r(uint32_t* r, uint32_t a) {
    asm volatile("ldmatrix.sync.aligned.m8n8.x4.shared.b16 {%0,%1,%2,%3},[%4];\n"
                 : "=r"(r[0]), "=r"(r[1]), "=r"(r[2]), "=r"(r[3]) : "r"(a));
}
__device__ __forceinline__ void ldm_x2r(uint32_t* r, uint32_t a) {
    asm volatile("ldmatrix.sync.aligned.m8n8.x2.shared.b16 {%0,%1},[%2];\n"
                 : "=r"(r[0]), "=r"(r[1]) : "r"(a));
}
// bf16 MMA (attention)
__device__ __forceinline__ void mma_bf16(float* c, const uint32_t* a, const uint32_t* b) {
    asm volatile(
        "mma.sync.aligned.m16n8k16.row.col.f32.bf16.bf16.f32 "
        "{%0,%1,%2,%3},{%4,%5,%6,%7},{%8,%9},{%0,%1,%2,%3};\n"
        : "+f"(c[0]), "+f"(c[1]), "+f"(c[2]), "+f"(c[3])
        : "r"(a[0]), "r"(a[1]), "r"(a[2]), "r"(a[3]), "r"(b[0]), "r"(b[1]));
}
// fp16 MMA (GEMMs)
__device__ __forceinline__ void mma_fp16(float* c, const uint32_t* a, const uint32_t* b) {
    asm volatile(
        "mma.sync.aligned.m16n8k16.row.col.f32.f16.f16.f32 "
        "{%0,%1,%2,%3},{%4,%5,%6,%7},{%8,%9},{%0,%1,%2,%3};\n"
        : "+f"(c[0]), "+f"(c[1]), "+f"(c[2]), "+f"(c[3])
        : "r"(a[0]), "r"(a[1]), "r"(a[2]), "r"(a[3]), "r"(b[0]), "r"(b[1]));
}
// bf16 split-pack (qkv epilogue)
__device__ __forceinline__ void splitpack2(float a, float b, uint32_t& hi, uint32_t& lo) {
    __nv_bfloat16 ha = __float2bfloat16_rn(a);
    __nv_bfloat16 hb = __float2bfloat16_rn(b);
    __nv_bfloat16 la = __float2bfloat16_rn(a - __bfloat162float(ha));
    __nv_bfloat16 lb = __float2bfloat16_rn(b - __bfloat162float(hb));
    hi = (uint32_t)(*(uint16_t*)&ha) | ((uint32_t)(*(uint16_t*)&hb) << 16);
    lo = (uint32_t)(*(uint16_t*)&la) | ((uint32_t)(*(uint16_t*)&lb) << 16);
}
// fp16 split-pack (attention epilogue -> proj GEMM input)
__device__ __forceinline__ void splitpack2h(float a, float b, uint32_t& hi, uint32_t& lo) {
    __half ha = __float2half_rn(a);
    __half hb = __float2half_rn(b);
    __half la = __float2half_rn(a - __half2float(ha));
    __half lb = __float2half_rn(b - __half2float(hb));
    hi = (uint32_t)(*(uint16_t*)&ha) | ((uint32_t)(*(uint16_t*)&hb) << 16);
    lo = (uint32_t)(*(uint16_t*)&la) | ((uint32_t)(*(uint16_t*)&lb) << 16);
}

// ---------------------------------------------------------------------------
// Split conversion: fp32 -> hi + lo fp16
// ---------------------------------------------------------------------------
__global__ __launch_bounds__(256)
void split_kernel(const float* __restrict__ in, __half* __restrict__ hi,
                  __half* __restrict__ lo, int n4)
{
    int i = blockIdx.x * blockDim.x + threadIdx.x;
    if (i >= n4) return;
    float4 v = ((const float4*)in)[i];
    __half h[4], l[4];
    float vv[4] = {v.x, v.y, v.z, v.w};
    #pragma unroll
    for (int j = 0; j < 4; ++j) {
        h[j] = __float2half_rn(vv[j]);
        l[j] = __float2half_rn(vv[j] - __half2float(h[j]));
    }
    ((uint2*)hi)[i] = *(uint2*)h;
    ((uint2*)lo)[i] = *(uint2*)l;
}

// ---------------------------------------------------------------------------
// Split + transpose: W [K][N] fp32 -> hiT, loT [N][K] fp16
// ---------------------------------------------------------------------------
__global__ __launch_bounds__(256)
void split_transpose_kernel(const float* __restrict__ W,
                            __half* __restrict__ hiT,
                            __half* __restrict__ loT, int K, int N)
{
    __shared__ float t[32][33];
    int n0 = blockIdx.x * 32;
    int k0 = blockIdx.y * 32;
    int tx = threadIdx.x, ty = threadIdx.y;   // 32 x 8
    #pragma unroll
    for (int r = 0; r < 32; r += 8)
        t[ty + r][tx] = W[(size_t)(k0 + ty + r) * N + n0 + tx];
    __syncthreads();
    #pragma unroll
    for (int r = 0; r < 32; r += 8) {
        float v = t[tx][ty + r];
        __half h = __float2half_rn(v);
        __half l = __float2half_rn(v - __half2float(h));
        size_t o = (size_t)(n0 + ty + r) * K + k0 + tx;
        hiT[o] = h;
        loT[o] = l;
    }
}

// ---------------------------------------------------------------------------
// 2-term fp16 mma.sync GEMM:  C = Ah·Bh^T + Al·Bh^T + bias  (B lo dropped;
// error ~2^-12·sqrt2 ≈ 3e-4, within the 1e-3 budget).
// 3-stage cp.async, SW128-swizzled tiles, hoisted addresses, A per-mt
// consumption, prefetch interleaved. Tile 128x128x32, 256 threads, 2 CTAs/SM.
// Stage: A rows 128x128B (hi chunks 0-3, lo 4-7), B rows 128x128B (hi 0-3).
// ---------------------------------------------------------------------------
#define GBM 128
#define GBN 128
#define GBK 32
#define TKB 32768                      // stage bytes (16KB A + 16KB B region)
#define NSTAGE 3
#define GEMM_SMEM_BYTES (NSTAGE * TKB) // 98304 B

__global__ __launch_bounds__(256, 2)
void gemm_split_fp16(const __half* __restrict__ Ah_g,
                     const __half* __restrict__ Al_g,
                     const __half* __restrict__ Bh_g,
                     const float* __restrict__ bias,
                     float* __restrict__ Cf,
                     __nv_bfloat16* __restrict__ Chi,
                     __nv_bfloat16* __restrict__ Clo,
                     int M, int N, int K)
{
    extern __shared__ char smem[];
    const uint32_t smem32 = (uint32_t)__cvta_generic_to_shared(smem);
    const int tid  = threadIdx.x;
    const int bm   = blockIdx.y * GBM;
    const int bn   = blockIdx.x * GBN;
    const int warp = tid >> 5, lane = tid & 31;
    const int wm   = (warp & 1) * 64;
    const int wn   = (warp >> 1) * 32;

    float acc[4][4][4];
    #pragma unroll
    for (int i = 0; i < 4; ++i)
        #pragma unroll
        for (int j = 0; j < 4; ++j)
            #pragma unroll
            for (int r = 0; r < 4; ++r) acc[i][j][r] = 0.f;

    // slices: p=0,1 -> A rows (hi+lo, 2 cp16/thread); p=2,3 -> B rows (hi, 1 cp16)
    auto load_part = [&](int s, int k0, int p) {
        uint32_t st = smem32 + s * TKB;
        if (p < 2) {
            int c = tid + p * 256;
            int row = c >> 2, cc = c & 3;
            size_t g = (size_t)(bm + row) * K + k0 + cc * 8;
            uint32_t d = st + row * 128 + ((cc ^ (row & 7)) * 16);
            cp16r(d,      Ah_g + g);
            cp16r(d ^ 64, Al_g + g);
        } else {
            int c = tid + (p - 2) * 256;
            int row = c >> 2, cc = c & 3;
            size_t g = (size_t)(bn + row) * K + k0 + cc * 8;
            uint32_t d = st + 16384 + row * 128 + ((cc ^ (row & 7)) * 16);
            cp16r(d, Bh_g + g);
        }
    };

    const int niter = K / GBK;
    #pragma unroll
    for (int p = 0; p < 4; ++p) load_part(0, 0, p);
    cp_commit();
    #pragma unroll
    for (int p = 0; p < 4; ++p) load_part(1, GBK, p);
    cp_commit();

    const int arow0 = wm + (lane & 15);
    const int brow0 = wn + (lane & 7);
    const int ac0   = lane >> 4;
    const int bc0   = (lane >> 3) & 1;

    int sc = 0, sn = 2;
    for (int it = 0; it < niter; ++it) {
        if (it + 1 < niter) cp_wait<1>(); else cp_wait<0>();
        __syncthreads();

        uint32_t aab = smem32 + sc * TKB;
        uint32_t aA[4], bA[4];
        #pragma unroll
        for (int mt = 0; mt < 4; ++mt) {
            int row = arow0 + mt * 16;
            aA[mt] = aab + row * 128 + ((ac0 ^ (row & 7)) * 16);
        }
        #pragma unroll
        for (int nt = 0; nt < 4; ++nt) {
            int row = brow0 + nt * 8;
            bA[nt] = aab + 16384 + row * 128 + ((bc0 ^ (row & 7)) * 16);
        }

        const bool pf  = (it + 2 < niter);
        const int  nk0 = (it + 2) * GBK;

        #pragma unroll
        for (int half = 0; half < 2; ++half) {
            const uint32_t ko = half * 32;

            uint32_t bfh[4][2];
            #pragma unroll
            for (int nt = 0; nt < 4; ++nt)
                ldm_x2r(bfh[nt], bA[nt] ^ ko);

            // hi-A term (hh)
            #pragma unroll
            for (int mt = 0; mt < 4; ++mt) {
                uint32_t afh[4];
                ldm_x4r(afh, aA[mt] ^ ko);
                if (pf && mt == 1) load_part(sn, nk0, half * 2);
                #pragma unroll
                for (int nt = 0; nt < 4; ++nt)
                    mma_fp16(acc[mt][nt], afh, bfh[nt]);
            }
            // lo-A term (lh)
            #pragma unroll
            for (int mt = 0; mt < 4; ++mt) {
                uint32_t afl[4];
                ldm_x4r(afl, aA[mt] ^ ko ^ 64);
                if (pf && mt == 1) load_part(sn, nk0, half * 2 + 1);
                #pragma unroll
                for (int nt = 0; nt < 4; ++nt)
                    mma_fp16(acc[mt][nt], afl, bfh[nt]);
            }
        }
        if (pf) cp_commit();
        sc = (sc + 1 == NSTAGE) ? 0 : sc + 1;
        sn = (sn + 1 == NSTAGE) ? 0 : sn + 1;
    }

    // Epilogue: bias + store (fp32 out, or bf16 hi/lo for attention)
    #pragma unroll
    for (int mt = 0; mt < 4; ++mt) {
        int r0 = bm + wm + mt * 16 + (lane >> 2);
        #pragma unroll
        for (int nt = 0; nt < 4; ++nt) {
            int cc = bn + wn + nt * 8 + (lane & 3) * 2;
            float b0 = bias[cc], b1 = bias[cc + 1];
            float v0 = acc[mt][nt][0] + b0, v1 = acc[mt][nt][1] + b1;
            float v2 = acc[mt][nt][2] + b0, v3 = acc[mt][nt][3] + b1;
            if (Cf) {
                *(float2*)(Cf + (size_t)r0 * N + cc)       = make_float2(v0, v1);
                *(float2*)(Cf + (size_t)(r0 + 8) * N + cc) = make_float2(v2, v3);
            } else {
                uint32_t h01, l01, h23, l23;
                splitpack2(v0, v1, h01, l01);
                splitpack2(v2, v3, h23, l23);
                *(uint32_t*)(Chi + (size_t)r0 * N + cc)       = h01;
                *(uint32_t*)(Clo + (size_t)r0 * N + cc)       = l01;
                *(uint32_t*)(Chi + (size_t)(r0 + 8) * N + cc) = h23;
                *(uint32_t*)(Clo + (size_t)(r0 + 8) * N + cc) = l23;
            }
        }
    }
}

// ---------------------------------------------------------------------------
// Tensor-core causal flash attention, split-bf16 3-term (unchanged compute,
// R13 passing version). Epilogue now emits fp16 hi/lo for the proj GEMM.
// ---------------------------------------------------------------------------
#define AROW  72
#define QTILE (128 * AROW)
#define KTILE (64 * AROW)
#define ASTG  (4 * KTILE)
#define FLASH_SMEM_BYTES ((2 * QTILE + 2 * ASTG) * 2)   // 110592 B

__global__ __launch_bounds__(256, 2)
void flash_attn_tc(const __nv_bfloat16* __restrict__ qkvh,
                   const __nv_bfloat16* __restrict__ qkvl,
                   __half* __restrict__ yh,
                   __half* __restrict__ yl)
{
    extern __shared__ __nv_bfloat16 sm[];
    __nv_bfloat16* Qh = sm;
    __nv_bfloat16* Ql = sm + QTILE;
    __nv_bfloat16* KV = sm + 2 * QTILE;

    const int qb = gridDim.x - 1 - blockIdx.x;
    const int h  = blockIdx.y;
    const int b  = blockIdx.z;
    const int q0 = qb * 128;
    const int tid = threadIdx.x, warp = tid >> 5, lane = tid & 31;

    const size_t rstride = (size_t)3 * CDIM;
    const size_t base = (size_t)b * T_SEQ * rstride + (size_t)h * HD;

    for (int i = tid; i < 1024; i += 256) {
        int r = i >> 3, ch = i & 7;
        size_t g = base + (size_t)(q0 + r) * rstride + ch * 8;
        cp16(Qh + r * AROW + ch * 8, qkvh + g);
        cp16(Ql + r * AROW + ch * 8, qkvl + g);
    }
    cp_commit();

    auto load_kv = [&](int s, int k0) {
        __nv_bfloat16* Kh = KV + s * ASTG;
        __nv_bfloat16* Kl = Kh + KTILE;
        __nv_bfloat16* Vh = Kl + KTILE;
        __nv_bfloat16* Vl = Vh + KTILE;
        for (int i = tid; i < 512; i += 256) {
            int r = i >> 3, ch = i & 7;
            size_t gk = base + CDIM + (size_t)(k0 + r) * rstride + ch * 8;
            size_t gv = gk + CDIM;
            cp16(Kh + r * AROW + ch * 8, qkvh + gk);
            cp16(Kl + r * AROW + ch * 8, qkvl + gk);
            cp16(Vh + r * AROW + ch * 8, qkvh + gv);
            cp16(Vl + r * AROW + ch * 8, qkvl + gv);
        }
    };
    load_kv(0, 0);
    cp_commit();

    float o[8][4];
    #pragma unroll
    for (int nb = 0; nb < 8; ++nb)
        #pragma unroll
        for (int r = 0; r < 4; ++r) o[nb][r] = 0.f;
    float m0 = -1e30f, m1 = -1e30f, l0 = 0.f, l1 = 0.f;

    const float SC = 0.125f * 1.4426950408889634f;
    const int rin   = lane >> 2;
    const int qrow0 = q0 + warp * 16 + rin;
    const int qrow1 = qrow0 + 8;
    const int cbase = 2 * (lane & 3);

    const int krow_x4 = ((lane >> 4) & 1) * 8 + (lane & 7);
    const int kcol_x4 = ((lane >> 3) & 1) * 8;
    const int vrow_x4 = lane & 15;
    const int vcol_x4 = ((lane >> 4) & 1) * 8;

    const int nkt = 2 * qb + 2;
    for (int kt = 0; kt < nkt; ++kt) {
        cp_wait<0>();
        __syncthreads();
        if (kt + 1 < nkt) { load_kv((kt + 1) & 1, (kt + 1) * 64); cp_commit(); }

        const __nv_bfloat16* Kh = KV + (kt & 1) * ASTG;
        const __nv_bfloat16* Kl = Kh + KTILE;
        const __nv_bfloat16* Vh = Kl + KTILE;
        const __nv_bfloat16* Vl = Vh + KTILE;

        float s[8][4];
        #pragma unroll
        for (int nb = 0; nb < 8; ++nb)
            #pragma unroll
            for (int r = 0; r < 4; ++r) s[nb][r] = 0.f;

        #pragma unroll
        for (int ks = 0; ks < 4; ++ks) {
            const int aoff = (warp * 16 + (lane & 15)) * AROW + ks * 16 + (lane >> 4) * 8;
            uint32_t ah[4], al[4];
            ldm_x4(ah, Qh + aoff);
            ldm_x4(al, Ql + aoff);
            #pragma unroll
            for (int nbp = 0; nbp < 4; ++nbp) {
                const int koff = (nbp * 16 + krow_x4) * AROW + ks * 16 + kcol_x4;
                uint32_t kh[4], kl[4];
                ldm_x4(kh, Kh + koff);
                ldm_x4(kl, Kl + koff);
                mma_bf16(s[2*nbp  ], ah, &kh[0]);
                mma_bf16(s[2*nbp+1], ah, &kh[2]);
                mma_bf16(s[2*nbp  ], ah, &kl[0]);
                mma_bf16(s[2*nbp+1], ah, &kl[2]);
                mma_bf16(s[2*nbp  ], al, &kh[0]);
                mma_bf16(s[2*nbp+1], al, &kh[2]);
            }
        }

        const int k0 = kt * 64;
        if (kt >= 2 * qb) {
            #pragma unroll
            for (int nb = 0; nb < 8; ++nb) {
                int c0 = k0 + nb * 8 + cbase;
                s[nb][0] = (c0     <= qrow0) ? s[nb][0] * SC : -1e30f;
                s[nb][1] = (c0 + 1 <= qrow0) ? s[nb][1] * SC : -1e30f;
                s[nb][2] = (c0     <= qrow1) ? s[nb][2] * SC : -1e30f;
                s[nb][3] = (c0 + 1 <= qrow1) ? s[nb][3] * SC : -1e30f;
            }
        } else {
            #pragma unroll
            for (int nb = 0; nb < 8; ++nb)
                #pragma unroll
                for (int r = 0; r < 4; ++r) s[nb][r] *= SC;
        }

        float mx0 = -1e30f, mx1 = -1e30f;
        #pragma unroll
        for (int nb = 0; nb < 8; ++nb) {
            mx0 = fmaxf(mx0, fmaxf(s[nb][0], s[nb][1]));
            mx1 = fmaxf(mx1, fmaxf(s[nb][2], s[nb][3]));
        }
        mx0 = fmaxf(mx0, __shfl_xor_sync(0xffffffffu, mx0, 1));
        mx0 = fmaxf(mx0, __shfl_xor_sync(0xffffffffu, mx0, 2));
        mx1 = fmaxf(mx1, __shfl_xor_sync(0xffffffffu, mx1, 1));
        mx1 = fmaxf(mx1, __shfl_xor_sync(0xffffffffu, mx1, 2));

        float nm0 = fmaxf(m0, mx0), nm1 = fmaxf(m1, mx1);
        float sc0 = exp2f(m0 - nm0), sc1 = exp2f(m1 - nm1);
        m0 = nm0; m1 = nm1;

        float rs0 = 0.f, rs1 = 0.f;
        #pragma unroll
        for (int nb = 0; nb < 8; ++nb) {
            s[nb][0] = exp2f(s[nb][0] - nm0);
            s[nb][1] = exp2f(s[nb][1] - nm0);
            s[nb][2] = exp2f(s[nb][2] - nm1);
            s[nb][3] = exp2f(s[nb][3] - nm1);
            rs0 += s[nb][0] + s[nb][1];
            rs1 += s[nb][2] + s[nb][3];
        }

        #pragma unroll
        for (int nb = 0; nb < 8; ++nb) {
            o[nb][0] *= sc0; o[nb][1] *= sc0;
            o[nb][2] *= sc1; o[nb][3] *= sc1;
        }

        #pragma unroll
        for (int t = 0; t < 4; ++t) {
            uint32_t ph[4], pl[4];
            splitpack2(s[2*t  ][0], s[2*t  ][1], ph[0], pl[0]);
            splitpack2(s[2*t  ][2], s[2*t  ][3], ph[1], pl[1]);
            splitpack2(s[2*t+1][0], s[2*t+1][1], ph[2], pl[2]);
            splitpack2(s[2*t+1][2], s[2*t+1][3], ph[3], pl[3]);
            const int vbase = (t * 16 + vrow_x4) * AROW;
            #pragma unroll
            for (int nbp = 0; nbp < 4; ++nbp) {
                const int voff = vbase + nbp * 16 + vcol_x4;
                uint32_t vh[4], vl[4];
                ldm_x4t(vh, Vh + voff);
                ldm_x4t(vl, Vl + voff);
                mma_bf16(o[2*nbp  ], ph, &vh[0]);
                mma_bf16(o[2*nbp+1], ph, &vh[2]);
                mma_bf16(o[2*nbp  ], ph, &vl[0]);
                mma_bf16(o[2*nbp+1], ph, &vl[2]);
                mma_bf16(o[2*nbp  ], pl, &vh[0]);
                mma_bf16(o[2*nbp+1], pl, &vh[2]);
            }
        }

        rs0 += __shfl_xor_sync(0xffffffffu, rs0, 1);
        rs0 += __shfl_xor_sync(0xffffffffu, rs0, 2);
        rs1 += __shfl_xor_sync(0xffffffffu, rs1, 1);
        rs1 += __shfl_xor_sync(0xffffffffu, rs1, 2);
        l0 = l0 * sc0 + rs0;
        l1 = l1 * sc1 + rs1;
    }

    float inv0 = 1.f / l0, inv1 = 1.f / l1;
    const size_t row0 = (size_t)b * T_SEQ + qrow0;
    const size_t row1 = (size_t)b * T_SEQ + qrow1;
    #pragma unroll
    for (int nb = 0; nb < 8; ++nb) {
        int cc = h * HD + nb * 8 + cbase;
        uint32_t h01, l01, h23, l23;
        splitpack2h(o[nb][0] * inv0, o[nb][1] * inv0, h01, l01);
        splitpack2h(o[nb][2] * inv1, o[nb][3] * inv1, h23, l23);
        *(uint32_t*)(yh + row0 * CDIM + cc) = h01;
        *(uint32_t*)(yl + row0 * CDIM + cc) = l01;
        *(uint32_t*)(yh + row1 * CDIM + cc) = h23;
        *(uint32_t*)(yl + row1 * CDIM + cc) = l23;
    }
}

// ---------------------------------------------------------------------------
// kernel_launch
// ---------------------------------------------------------------------------
extern "C" void kernel_launch(void* const* d_in, const int* in_sizes, int n_in,
                              void* d_out, int out_size)
{
    (void)in_sizes; (void)n_in; (void)out_size;
    const float* x      = (const float*)d_in[0];
    const float* W_attn = (const float*)d_in[1];
    const float* b_attn = (const float*)d_in[2];
    const float* W_proj = (const float*)d_in[3];
    const float* b_proj = (const float*)d_in[4];
    float* out = (float*)d_out;

    __half *xh, *xl, *yh, *yl, *wah, *wal, *wph, *wpl;
    __nv_bfloat16 *qkvh, *qkvl;
    cudaGetSymbolAddress((void**)&xh,   g_xh);
    cudaGetSymbolAddress((void**)&xl,   g_xl);
    cudaGetSymbolAddress((void**)&qkvh, g_qkvh);
    cudaGetSymbolAddress((void**)&qkvl, g_qkvl);
    cudaGetSymbolAddress((void**)&yh,   g_yh);
    cudaGetSymbolAddress((void**)&yl,   g_yl);
    cudaGetSymbolAddress((void**)&wah,  g_wah);
    cudaGetSymbolAddress((void**)&wal,  g_wal);
    cudaGetSymbolAddress((void**)&wph,  g_wph);
    cudaGetSymbolAddress((void**)&wpl,  g_wpl);
    (void)wal; (void)wpl;   // lo-B unused by 2-term GEMM (kept for symmetry)

    cudaFuncSetAttribute(gemm_split_fp16, cudaFuncAttributeMaxDynamicSharedMemorySize,
                         GEMM_SMEM_BYTES);
    cudaFuncSetAttribute(flash_attn_tc, cudaFuncAttributeMaxDynamicSharedMemorySize,
                         FLASH_SMEM_BYTES);

    // 1) split x (fp16 hi/lo)
    {
        int n4 = MROWS * CDIM / 4;
        split_kernel<<<(n4 + 255) / 256, 256>>>(x, xh, xl, n4);
    }
    // 2) split + transpose weights (fp16; only hi consumed by 2-term GEMM)
    {
        dim3 blk(32, 8);
        split_transpose_kernel<<<dim3(3 * CDIM / 32, CDIM / 32), blk>>>(W_attn, wah, wal, CDIM, 3 * CDIM);
        split_transpose_kernel<<<dim3(CDIM / 32, CDIM / 32), blk>>>(W_proj, wph, wpl, CDIM, CDIM);
    }
    // 3) qkv(bf16 hi/lo) = split(x @ W_attn + b_attn)   [8192, 3072]
    {
        dim3 grid(3 * CDIM / GBN, MROWS / GBM);   // (24, 64)
        gemm_split_fp16<<<grid, 256, GEMM_SMEM_BYTES>>>(xh, xl, wah, b_attn,
                                                        nullptr, qkvh, qkvl,
                                                        MROWS, 3 * CDIM, CDIM);
    }
    // 4) tensor-core flash attention -> yh/yl (fp16 hi/lo)
    {
        dim3 grid(T_SEQ / 128, NHEAD, BATCH);
        flash_attn_tc<<<grid, 256, FLASH_SMEM_BYTES>>>(qkvh, qkvl, yh, yl);
    }
    // 5) out = y @ W_proj + b_proj   [8192, 1024] fp32
    {
        dim3 grid(CDIM / GBN, MROWS / GBM);       // (8, 64)
        gemm_split_fp16<<<grid, 256, GEMM_SMEM_BYTES>>>(yh, yl, wph, b_proj,
                                                        out, nullptr, nullptr,
                                                        MROWS, CDIM, CDIM);
    }
}

// round 16
// speedup vs baseline: 1.4446x; 1.1595x over previous
#include <cuda_runtime.h>
#include <cuda_bf16.h>
#include <cuda_fp16.h>
#include <math.h>
#include <stdint.h>

// Problem constants
#define BATCH   4
#define T_SEQ   2048
#define CDIM    1024
#define NHEAD   16
#define HD      64
#define MROWS   (BATCH * T_SEQ)  // 8192

// ---------------------------------------------------------------------------
// Scratch (allocation-free rule: __device__ globals)
// ---------------------------------------------------------------------------
__device__ __half g_xh[(size_t)MROWS * CDIM];
__device__ __half g_xl[(size_t)MROWS * CDIM];
__device__ __half g_qkvh[(size_t)MROWS * 3 * CDIM];   // fp16 pair (attention in)
__device__ __half g_qkvl[(size_t)MROWS * 3 * CDIM];
__device__ __half g_yh[(size_t)MROWS * CDIM];
__device__ __half g_yl[(size_t)MROWS * CDIM];
__device__ __half g_wah[(size_t)3 * CDIM * CDIM];     // W_attn^T fp16 [3072][1024]
__device__ __half g_wal[(size_t)3 * CDIM * CDIM];
__device__ __half g_wph[(size_t)CDIM * CDIM];
__device__ __half g_wpl[(size_t)CDIM * CDIM];

// ---------------------------------------------------------------------------
// PTX helpers (sm_103-safe set only: cp.async / ldmatrix / mma.sync)
// ---------------------------------------------------------------------------
__device__ __forceinline__ void cp16(void* dst, const void* src) {
    uint32_t d = (uint32_t)__cvta_generic_to_shared(dst);
    asm volatile("cp.async.cg.shared.global [%0], [%1], 16;\n" :: "r"(d), "l"(src));
}
__device__ __forceinline__ void cp16r(uint32_t d, const void* src) {
    asm volatile("cp.async.cg.shared.global [%0], [%1], 16;\n" :: "r"(d), "l"(src));
}
__device__ __forceinline__ void cp_commit() {
    asm volatile("cp.async.commit_group;\n" ::: "memory");
}
template <int N> __device__ __forceinline__ void cp_wait() {
    asm volatile("cp.async.wait_group %0;\n" :: "n"(N) : "memory");
}
__device__ __forceinline__ void ldm_x4(uint32_t* r, const void* p) {
    uint32_t a = (uint32_t)__cvta_generic_to_shared(p);
    asm volatile("ldmatrix.sync.aligned.m8n8.x4.shared.b16 {%0,%1,%2,%3},[%4];\n"
                 : "=r"(r[0]), "=r"(r[1]), "=r"(r[2]), "=r"(r[3]) : "r"(a));
}
__device__ __forceinline__ void ldm_x4t(uint32_t* r, const void* p) {
    uint32_t a = (uint32_t)__cvta_generic_to_shared(p);
    asm volatile("ldmatrix.sync.aligned.m8n8.x4.trans.shared.b16 {%0,%1,%2,%3},[%4];\n"
                 : "=r"(r[0]), "=r"(r[1]), "=r"(r[2]), "=r"(r[3]) : "r"(a));
}
__device__ __forceinline__ void ldm_x4r(uint32_t* r, uint32_t a) {
    asm volatile("ldmatrix.sync.aligned.m8n8.x4.shared.b16 {%0,%1,%2,%3},[%4];\n"
                 : "=r"(r[0]), "=r"(r[1]), "=r"(r[2]), "=r"(r[3]) : "r"(a));
}
__device__ __forceinline__ void ldm_x2r(uint32_t* r, uint32_t a) {
    asm volatile("ldmatrix.sync.aligned.m8n8.x2.shared.b16 {%0,%1},[%2];\n"
                 : "=r"(r[0]), "=r"(r[1]) : "r"(a));
}
// fp16 MMA
__device__ __forceinline__ void mma_fp16(float* c, const uint32_t* a, const uint32_t* b) {
    asm volatile(
        "mma.sync.aligned.m16n8k16.row.col.f32.f16.f16.f32 "
        "{%0,%1,%2,%3},{%4,%5,%6,%7},{%8,%9},{%0,%1,%2,%3};\n"
        : "+f"(c[0]), "+f"(c[1]), "+f"(c[2]), "+f"(c[3])
        : "r"(a[0]), "r"(a[1]), "r"(a[2]), "r"(a[3]), "r"(b[0]), "r"(b[1]));
}
// fp16 split-pack
__device__ __forceinline__ void splitpack2h(float a, float b, uint32_t& hi, uint32_t& lo) {
    __half ha = __float2half_rn(a);
    __half hb = __float2half_rn(b);
    __half la = __float2half_rn(a - __half2float(ha));
    __half lb = __float2half_rn(b - __half2float(hb));
    hi = (uint32_t)(*(uint16_t*)&ha) | ((uint32_t)(*(uint16_t*)&hb) << 16);
    lo = (uint32_t)(*(uint16_t*)&la) | ((uint32_t)(*(uint16_t*)&lb) << 16);
}

// ---------------------------------------------------------------------------
// Split conversion: fp32 -> hi + lo fp16
// ---------------------------------------------------------------------------
__global__ __launch_bounds__(256)
void split_kernel(const float* __restrict__ in, __half* __restrict__ hi,
                  __half* __restrict__ lo, int n4)
{
    int i = blockIdx.x * blockDim.x + threadIdx.x;
    if (i >= n4) return;
    float4 v = ((const float4*)in)[i];
    __half h[4], l[4];
    float vv[4] = {v.x, v.y, v.z, v.w};
    #pragma unroll
    for (int j = 0; j < 4; ++j) {
        h[j] = __float2half_rn(vv[j]);
        l[j] = __float2half_rn(vv[j] - __half2float(h[j]));
    }
    ((uint2*)hi)[i] = *(uint2*)h;
    ((uint2*)lo)[i] = *(uint2*)l;
}

// ---------------------------------------------------------------------------
// Split + transpose: W [K][N] fp32 -> hiT, loT [N][K] fp16
// ---------------------------------------------------------------------------
__global__ __launch_bounds__(256)
void split_transpose_kernel(const float* __restrict__ W,
                            __half* __restrict__ hiT,
                            __half* __restrict__ loT, int K, int N)
{
    __shared__ float t[32][33];
    int n0 = blockIdx.x * 32;
    int k0 = blockIdx.y * 32;
    int tx = threadIdx.x, ty = threadIdx.y;   // 32 x 8
    #pragma unroll
    for (int r = 0; r < 32; r += 8)
        t[ty + r][tx] = W[(size_t)(k0 + ty + r) * N + n0 + tx];
    __syncthreads();
    #pragma unroll
    for (int r = 0; r < 32; r += 8) {
        float v = t[tx][ty + r];
        __half h = __float2half_rn(v);
        __half l = __float2half_rn(v - __half2float(h));
        size_t o = (size_t)(n0 + ty + r) * K + k0 + tx;
        hiT[o] = h;
        loT[o] = l;
    }
}

// ---------------------------------------------------------------------------
// 2-term fp16 mma.sync GEMM:  C = (Ah+Al)·Bh^T + bias  (R14 version, WIN)
// ---------------------------------------------------------------------------
#define GBM 128
#define GBN 128
#define GBK 32
#define TKB 32768
#define NSTAGE 3
#define GEMM_SMEM_BYTES (NSTAGE * TKB) // 98304 B

__global__ __launch_bounds__(256, 2)
void gemm_split_fp16(const __half* __restrict__ Ah_g,
                     const __half* __restrict__ Al_g,
                     const __half* __restrict__ Bh_g,
                     const float* __restrict__ bias,
                     float* __restrict__ Cf,
                     __half* __restrict__ Chi,
                     __half* __restrict__ Clo,
                     int M, int N, int K)
{
    extern __shared__ char smem[];
    const uint32_t smem32 = (uint32_t)__cvta_generic_to_shared(smem);
    const int tid  = threadIdx.x;
    const int bm   = blockIdx.y * GBM;
    const int bn   = blockIdx.x * GBN;
    const int warp = tid >> 5, lane = tid & 31;
    const int wm   = (warp & 1) * 64;
    const int wn   = (warp >> 1) * 32;

    float acc[4][4][4];
    #pragma unroll
    for (int i = 0; i < 4; ++i)
        #pragma unroll
        for (int j = 0; j < 4; ++j)
            #pragma unroll
            for (int r = 0; r < 4; ++r) acc[i][j][r] = 0.f;

    auto load_part = [&](int s, int k0, int p) {
        uint32_t st = smem32 + s * TKB;
        if (p < 2) {
            int c = tid + p * 256;
            int row = c >> 2, cc = c & 3;
            size_t g = (size_t)(bm + row) * K + k0 + cc * 8;
            uint32_t d = st + row * 128 + ((cc ^ (row & 7)) * 16);
            cp16r(d,      Ah_g + g);
            cp16r(d ^ 64, Al_g + g);
        } else {
            int c = tid + (p - 2) * 256;
            int row = c >> 2, cc = c & 3;
            size_t g = (size_t)(bn + row) * K + k0 + cc * 8;
            uint32_t d = st + 16384 + row * 128 + ((cc ^ (row & 7)) * 16);
            cp16r(d, Bh_g + g);
        }
    };

    const int niter = K / GBK;
    #pragma unroll
    for (int p = 0; p < 4; ++p) load_part(0, 0, p);
    cp_commit();
    #pragma unroll
    for (int p = 0; p < 4; ++p) load_part(1, GBK, p);
    cp_commit();

    const int arow0 = wm + (lane & 15);
    const int brow0 = wn + (lane & 7);
    const int ac0   = lane >> 4;
    const int bc0   = (lane >> 3) & 1;

    int sc = 0, sn = 2;
    for (int it = 0; it < niter; ++it) {
        if (it + 1 < niter) cp_wait<1>(); else cp_wait<0>();
        __syncthreads();

        uint32_t aab = smem32 + sc * TKB;
        uint32_t aA[4], bA[4];
        #pragma unroll
        for (int mt = 0; mt < 4; ++mt) {
            int row = arow0 + mt * 16;
            aA[mt] = aab + row * 128 + ((ac0 ^ (row & 7)) * 16);
        }
        #pragma unroll
        for (int nt = 0; nt < 4; ++nt) {
            int row = brow0 + nt * 8;
            bA[nt] = aab + 16384 + row * 128 + ((bc0 ^ (row & 7)) * 16);
        }

        const bool pf  = (it + 2 < niter);
        const int  nk0 = (it + 2) * GBK;

        #pragma unroll
        for (int half = 0; half < 2; ++half) {
            const uint32_t ko = half * 32;

            uint32_t bfh[4][2];
            #pragma unroll
            for (int nt = 0; nt < 4; ++nt)
                ldm_x2r(bfh[nt], bA[nt] ^ ko);

            #pragma unroll
            for (int mt = 0; mt < 4; ++mt) {
                uint32_t afh[4];
                ldm_x4r(afh, aA[mt] ^ ko);
                if (pf && mt == 1) load_part(sn, nk0, half * 2);
                #pragma unroll
                for (int nt = 0; nt < 4; ++nt)
                    mma_fp16(acc[mt][nt], afh, bfh[nt]);
            }
            #pragma unroll
            for (int mt = 0; mt < 4; ++mt) {
                uint32_t afl[4];
                ldm_x4r(afl, aA[mt] ^ ko ^ 64);
                if (pf && mt == 1) load_part(sn, nk0, half * 2 + 1);
                #pragma unroll
                for (int nt = 0; nt < 4; ++nt)
                    mma_fp16(acc[mt][nt], afl, bfh[nt]);
            }
        }
        if (pf) cp_commit();
        sc = (sc + 1 == NSTAGE) ? 0 : sc + 1;
        sn = (sn + 1 == NSTAGE) ? 0 : sn + 1;
    }

    // Epilogue: bias + store (fp32 out, or fp16 hi/lo)
    #pragma unroll
    for (int mt = 0; mt < 4; ++mt) {
        int r0 = bm + wm + mt * 16 + (lane >> 2);
        #pragma unroll
        for (int nt = 0; nt < 4; ++nt) {
            int cc = bn + wn + nt * 8 + (lane & 3) * 2;
            float b0 = bias[cc], b1 = bias[cc + 1];
            float v0 = acc[mt][nt][0] + b0, v1 = acc[mt][nt][1] + b1;
            float v2 = acc[mt][nt][2] + b0, v3 = acc[mt][nt][3] + b1;
            if (Cf) {
                *(float2*)(Cf + (size_t)r0 * N + cc)       = make_float2(v0, v1);
                *(float2*)(Cf + (size_t)(r0 + 8) * N + cc) = make_float2(v2, v3);
            } else {
                uint32_t h01, l01, h23, l23;
                splitpack2h(v0, v1, h01, l01);
                splitpack2h(v2, v3, h23, l23);
                *(uint32_t*)(Chi + (size_t)r0 * N + cc)       = h01;
                *(uint32_t*)(Clo + (size_t)r0 * N + cc)       = l01;
                *(uint32_t*)(Chi + (size_t)(r0 + 8) * N + cc) = h23;
                *(uint32_t*)(Clo + (size_t)(r0 + 8) * N + cc) = l23;
            }
        }
    }
}

// ---------------------------------------------------------------------------
// 2-term fp16 causal flash attention, BQ=128 (8 warps, 256 thr), 2 CTAs/SM.
//   S = (Qh+Ql)·Kh^T   (Kl never loaded)
//   O = (Ph+Pl)·Vh     (Vl never loaded)
// KV stage = Kh + Vh only (half the smem/cp.async/LDSM of the 3-term version).
// ---------------------------------------------------------------------------
#define AROW  72
#define QTILE (128 * AROW)
#define KTILE (64 * AROW)
#define ASTG  (2 * KTILE)                               // Kh, Vh per stage
#define FLASH_SMEM_BYTES ((2 * QTILE + 2 * ASTG) * 2)   // 73728 B

__global__ __launch_bounds__(256, 2)
void flash_attn_tc(const __half* __restrict__ qkvh,
                   const __half* __restrict__ qkvl,
                   __half* __restrict__ yh,
                   __half* __restrict__ yl)
{
    extern __shared__ __half sm[];
    __half* Qh = sm;
    __half* Ql = sm + QTILE;
    __half* KV = sm + 2 * QTILE;

    const int qb = gridDim.x - 1 - blockIdx.x;
    const int h  = blockIdx.y;
    const int b  = blockIdx.z;
    const int q0 = qb * 128;
    const int tid = threadIdx.x, warp = tid >> 5, lane = tid & 31;

    const size_t rstride = (size_t)3 * CDIM;
    const size_t base = (size_t)b * T_SEQ * rstride + (size_t)h * HD;

    for (int i = tid; i < 1024; i += 256) {
        int r = i >> 3, ch = i & 7;
        size_t g = base + (size_t)(q0 + r) * rstride + ch * 8;
        cp16(Qh + r * AROW + ch * 8, qkvh + g);
        cp16(Ql + r * AROW + ch * 8, qkvl + g);
    }
    cp_commit();

    auto load_kv = [&](int s, int k0) {
        __half* Kh = KV + s * ASTG;
        __half* Vh = Kh + KTILE;
        for (int i = tid; i < 512; i += 256) {
            int r = i >> 3, ch = i & 7;
            size_t gk = base + CDIM + (size_t)(k0 + r) * rstride + ch * 8;
            cp16(Kh + r * AROW + ch * 8, qkvh + gk);
            cp16(Vh + r * AROW + ch * 8, qkvh + gk + CDIM);
        }
    };
    load_kv(0, 0);
    cp_commit();

    float o[8][4];
    #pragma unroll
    for (int nb = 0; nb < 8; ++nb)
        #pragma unroll
        for (int r = 0; r < 4; ++r) o[nb][r] = 0.f;
    float m0 = -1e30f, m1 = -1e30f, l0 = 0.f, l1 = 0.f;

    const float SC = 0.125f * 1.4426950408889634f;
    const int rin   = lane >> 2;
    const int qrow0 = q0 + warp * 16 + rin;
    const int qrow1 = qrow0 + 8;
    const int cbase = 2 * (lane & 3);

    const int krow_x4 = ((lane >> 4) & 1) * 8 + (lane & 7);
    const int kcol_x4 = ((lane >> 3) & 1) * 8;
    const int vrow_x4 = lane & 15;
    const int vcol_x4 = ((lane >> 4) & 1) * 8;

    const int nkt = 2 * qb + 2;
    for (int kt = 0; kt < nkt; ++kt) {
        cp_wait<0>();
        __syncthreads();
        if (kt + 1 < nkt) { load_kv((kt + 1) & 1, (kt + 1) * 64); cp_commit(); }

        const __half* Kh = KV + (kt & 1) * ASTG;
        const __half* Vh = Kh + KTILE;

        float s[8][4];
        #pragma unroll
        for (int nb = 0; nb < 8; ++nb)
            #pragma unroll
            for (int r = 0; r < 4; ++r) s[nb][r] = 0.f;

        // ---- S = (Qh+Ql) Kh^T ----
        #pragma unroll
        for (int ks = 0; ks < 4; ++ks) {
            const int aoff = (warp * 16 + (lane & 15)) * AROW + ks * 16 + (lane >> 4) * 8;
            uint32_t ah[4], al[4];
            ldm_x4(ah, Qh + aoff);
            ldm_x4(al, Ql + aoff);
            #pragma unroll
            for (int nbp = 0; nbp < 4; ++nbp) {
                const int koff = (nbp * 16 + krow_x4) * AROW + ks * 16 + kcol_x4;
                uint32_t kh[4];
                ldm_x4(kh, Kh + koff);
                mma_fp16(s[2*nbp  ], ah, &kh[0]);
                mma_fp16(s[2*nbp+1], ah, &kh[2]);
                mma_fp16(s[2*nbp  ], al, &kh[0]);
                mma_fp16(s[2*nbp+1], al, &kh[2]);
            }
        }

        const int k0 = kt * 64;
        if (kt >= 2 * qb) {
            #pragma unroll
            for (int nb = 0; nb < 8; ++nb) {
                int c0 = k0 + nb * 8 + cbase;
                s[nb][0] = (c0     <= qrow0) ? s[nb][0] * SC : -1e30f;
                s[nb][1] = (c0 + 1 <= qrow0) ? s[nb][1] * SC : -1e30f;
                s[nb][2] = (c0     <= qrow1) ? s[nb][2] * SC : -1e30f;
                s[nb][3] = (c0 + 1 <= qrow1) ? s[nb][3] * SC : -1e30f;
            }
        } else {
            #pragma unroll
            for (int nb = 0; nb < 8; ++nb)
                #pragma unroll
                for (int r = 0; r < 4; ++r) s[nb][r] *= SC;
        }

        float mx0 = -1e30f, mx1 = -1e30f;
        #pragma unroll
        for (int nb = 0; nb < 8; ++nb) {
            mx0 = fmaxf(mx0, fmaxf(s[nb][0], s[nb][1]));
            mx1 = fmaxf(mx1, fmaxf(s[nb][2], s[nb][3]));
        }
        mx0 = fmaxf(mx0, __shfl_xor_sync(0xffffffffu, mx0, 1));
        mx0 = fmaxf(mx0, __shfl_xor_sync(0xffffffffu, mx0, 2));
        mx1 = fmaxf(mx1, __shfl_xor_sync(0xffffffffu, mx1, 1));
        mx1 = fmaxf(mx1, __shfl_xor_sync(0xffffffffu, mx1, 2));

        float nm0 = fmaxf(m0, mx0), nm1 = fmaxf(m1, mx1);
        float sc0 = exp2f(m0 - nm0), sc1 = exp2f(m1 - nm1);
        m0 = nm0; m1 = nm1;

        float rs0 = 0.f, rs1 = 0.f;
        #pragma unroll
        for (int nb = 0; nb < 8; ++nb) {
            s[nb][0] = exp2f(s[nb][0] - nm0);
            s[nb][1] = exp2f(s[nb][1] - nm0);
            s[nb][2] = exp2f(s[nb][2] - nm1);
            s[nb][3] = exp2f(s[nb][3] - nm1);
            rs0 += s[nb][0] + s[nb][1];
            rs1 += s[nb][2] + s[nb][3];
        }

        #pragma unroll
        for (int nb = 0; nb < 8; ++nb) {
            o[nb][0] *= sc0; o[nb][1] *= sc0;
            o[nb][2] *= sc1; o[nb][3] *= sc1;
        }

        // ---- O += (Ph+Pl) Vh ----
        #pragma unroll
        for (int t = 0; t < 4; ++t) {
            uint32_t ph[4], pl[4];
            splitpack2h(s[2*t  ][0], s[2*t  ][1], ph[0], pl[0]);
            splitpack2h(s[2*t  ][2], s[2*t  ][3], ph[1], pl[1]);
            splitpack2h(s[2*t+1][0], s[2*t+1][1], ph[2], pl[2]);
            splitpack2h(s[2*t+1][2], s[2*t+1][3], ph[3], pl[3]);
            const int vbase = (t * 16 + vrow_x4) * AROW;
            #pragma unroll
            for (int nbp = 0; nbp < 4; ++nbp) {
                const int voff = vbase + nbp * 16 + vcol_x4;
                uint32_t vh[4];
                ldm_x4t(vh, Vh + voff);
                mma_fp16(o[2*nbp  ], ph, &vh[0]);
                mma_fp16(o[2*nbp+1], ph, &vh[2]);
                mma_fp16(o[2*nbp  ], pl, &vh[0]);
                mma_fp16(o[2*nbp+1], pl, &vh[2]);
            }
        }

        rs0 += __shfl_xor_sync(0xffffffffu, rs0, 1);
        rs0 += __shfl_xor_sync(0xffffffffu, rs0, 2);
        rs1 += __shfl_xor_sync(0xffffffffu, rs1, 1);
        rs1 += __shfl_xor_sync(0xffffffffu, rs1, 2);
        l0 = l0 * sc0 + rs0;
        l1 = l1 * sc1 + rs1;
    }

    float inv0 = 1.f / l0, inv1 = 1.f / l1;
    const size_t row0 = (size_t)b * T_SEQ + qrow0;
    const size_t row1 = (size_t)b * T_SEQ + qrow1;
    #pragma unroll
    for (int nb = 0; nb < 8; ++nb) {
        int cc = h * HD + nb * 8 + cbase;
        uint32_t h01, l01, h23, l23;
        splitpack2h(o[nb][0] * inv0, o[nb][1] * inv0, h01, l01);
        splitpack2h(o[nb][2] * inv1, o[nb][3] * inv1, h23, l23);
        *(uint32_t*)(yh + row0 * CDIM + cc) = h01;
        *(uint32_t*)(yl + row0 * CDIM + cc) = l01;
        *(uint32_t*)(yh + row1 * CDIM + cc) = h23;
        *(uint32_t*)(yl + row1 * CDIM + cc) = l23;
    }
}

// ---------------------------------------------------------------------------
// kernel_launch
// ---------------------------------------------------------------------------
extern "C" void kernel_launch(void* const* d_in, const int* in_sizes, int n_in,
                              void* d_out, int out_size)
{
    (void)in_sizes; (void)n_in; (void)out_size;
    const float* x      = (const float*)d_in[0];
    const float* W_attn = (const float*)d_in[1];
    const float* b_attn = (const float*)d_in[2];
    const float* W_proj = (const float*)d_in[3];
    const float* b_proj = (const float*)d_in[4];
    float* out = (float*)d_out;

    __half *xh, *xl, *qkvh, *qkvl, *yh, *yl, *wah, *wal, *wph, *wpl;
    cudaGetSymbolAddress((void**)&xh,   g_xh);
    cudaGetSymbolAddress((void**)&xl,   g_xl);
    cudaGetSymbolAddress((void**)&qkvh, g_qkvh);
    cudaGetSymbolAddress((void**)&qkvl, g_qkvl);
    cudaGetSymbolAddress((void**)&yh,   g_yh);
    cudaGetSymbolAddress((void**)&yl,   g_yl);
    cudaGetSymbolAddress((void**)&wah,  g_wah);
    cudaGetSymbolAddress((void**)&wal,  g_wal);
    cudaGetSymbolAddress((void**)&wph,  g_wph);
    cudaGetSymbolAddress((void**)&wpl,  g_wpl);
    (void)wal; (void)wpl;   // lo-B unused by 2-term GEMM

    cudaFuncSetAttribute(gemm_split_fp16, cudaFuncAttributeMaxDynamicSharedMemorySize,
                         GEMM_SMEM_BYTES);
    cudaFuncSetAttribute(flash_attn_tc, cudaFuncAttributeMaxDynamicSharedMemorySize,
                         FLASH_SMEM_BYTES);

    // 1) split x (fp16 hi/lo)
    {
        int n4 = MROWS * CDIM / 4;
        split_kernel<<<(n4 + 255) / 256, 256>>>(x, xh, xl, n4);
    }
    // 2) split + transpose weights (fp16; only hi consumed)
    {
        dim3 blk(32, 8);
        split_transpose_kernel<<<dim3(3 * CDIM / 32, CDIM / 32), blk>>>(W_attn, wah, wal, CDIM, 3 * CDIM);
        split_transpose_kernel<<<dim3(CDIM / 32, CDIM / 32), blk>>>(W_proj, wph, wpl, CDIM, CDIM);
    }
    // 3) qkv(fp16 hi/lo) = split(x @ W_attn + b_attn)   [8192, 3072]
    {
        dim3 grid(3 * CDIM / GBN, MROWS / GBM);   // (24, 64)
        gemm_split_fp16<<<grid, 256, GEMM_SMEM_BYTES>>>(xh, xl, wah, b_attn,
                                                        nullptr, qkvh, qkvl,
                                                        MROWS, 3 * CDIM, CDIM);
    }
    // 4) 2-term fp16 flash attention -> yh/yl
    {
        dim3 grid(T_SEQ / 128, NHEAD, BATCH);
        flash_attn_tc<<<grid, 256, FLASH_SMEM_BYTES>>>(qkvh, qkvl, yh, yl);
    }
    // 5) out = y @ W_proj + b_proj   [8192, 1024] fp32
    {
        dim3 grid(CDIM / GBN, MROWS / GBM);       // (8, 64)
        gemm_split_fp16<<<grid, 256, GEMM_SMEM_BYTES>>>(yh, yl, wph, b_proj,
                                                        out, nullptr, nullptr,
                                                        MROWS, CDIM, CDIM);
    }
}

// round 17
// speedup vs baseline: 2.4113x; 1.6692x over previous
#include <cuda_runtime.h>
#include <cuda_fp16.h>
#include <math.h>
#include <stdint.h>

// Problem constants
#define BATCH   4
#define T_SEQ   2048
#define CDIM    1024
#define NHEAD   16
#define HD      64
#define MROWS   (BATCH * T_SEQ)  // 8192

// ---------------------------------------------------------------------------
// Scratch (allocation-free rule: __device__ globals)
// ---------------------------------------------------------------------------
__device__ __half g_x16[(size_t)MROWS * CDIM];
__device__ __half g_qkv16[(size_t)MROWS * 3 * CDIM];
__device__ __half g_y16[(size_t)MROWS * CDIM];
__device__ __half g_wa[(size_t)3 * CDIM * CDIM];   // W_attn^T fp16 [3072][1024]
__device__ __half g_wp[(size_t)CDIM * CDIM];       // W_proj^T fp16 [1024][1024]

// ---------------------------------------------------------------------------
// PTX helpers (sm_103-safe set only: cp.async / ldmatrix / mma.sync)
// ---------------------------------------------------------------------------
__device__ __forceinline__ void cp16(void* dst, const void* src) {
    uint32_t d = (uint32_t)__cvta_generic_to_shared(dst);
    asm volatile("cp.async.cg.shared.global [%0], [%1], 16;\n" :: "r"(d), "l"(src));
}
__device__ __forceinline__ void cp16r(uint32_t d, const void* src) {
    asm volatile("cp.async.cg.shared.global [%0], [%1], 16;\n" :: "r"(d), "l"(src));
}
__device__ __forceinline__ void cp_commit() {
    asm volatile("cp.async.commit_group;\n" ::: "memory");
}
template <int N> __device__ __forceinline__ void cp_wait() {
    asm volatile("cp.async.wait_group %0;\n" :: "n"(N) : "memory");
}
__device__ __forceinline__ void ldm_x4(uint32_t* r, const void* p) {
    uint32_t a = (uint32_t)__cvta_generic_to_shared(p);
    asm volatile("ldmatrix.sync.aligned.m8n8.x4.shared.b16 {%0,%1,%2,%3},[%4];\n"
                 : "=r"(r[0]), "=r"(r[1]), "=r"(r[2]), "=r"(r[3]) : "r"(a));
}
__device__ __forceinline__ void ldm_x4t(uint32_t* r, const void* p) {
    uint32_t a = (uint32_t)__cvta_generic_to_shared(p);
    asm volatile("ldmatrix.sync.aligned.m8n8.x4.trans.shared.b16 {%0,%1,%2,%3},[%4];\n"
                 : "=r"(r[0]), "=r"(r[1]), "=r"(r[2]), "=r"(r[3]) : "r"(a));
}
__device__ __forceinline__ void ldm_x4r(uint32_t* r, uint32_t a) {
    asm volatile("ldmatrix.sync.aligned.m8n8.x4.shared.b16 {%0,%1,%2,%3},[%4];\n"
                 : "=r"(r[0]), "=r"(r[1]), "=r"(r[2]), "=r"(r[3]) : "r"(a));
}
__device__ __forceinline__ void ldm_x2r(uint32_t* r, uint32_t a) {
    asm volatile("ldmatrix.sync.aligned.m8n8.x2.shared.b16 {%0,%1},[%2];\n"
                 : "=r"(r[0]), "=r"(r[1]) : "r"(a));
}
__device__ __forceinline__ void mma_fp16(float* c, const uint32_t* a, const uint32_t* b) {
    asm volatile(
        "mma.sync.aligned.m16n8k16.row.col.f32.f16.f16.f32 "
        "{%0,%1,%2,%3},{%4,%5,%6,%7},{%8,%9},{%0,%1,%2,%3};\n"
        : "+f"(c[0]), "+f"(c[1]), "+f"(c[2]), "+f"(c[3])
        : "r"(a[0]), "r"(a[1]), "r"(a[2]), "r"(a[3]), "r"(b[0]), "r"(b[1]));
}
__device__ __forceinline__ uint32_t pack2h(float a, float b) {
    __half2 h = __floats2half2_rn(a, b);
    return *(uint32_t*)&h;
}

// ---------------------------------------------------------------------------
// Convert fp32 -> fp16
// ---------------------------------------------------------------------------
__global__ __launch_bounds__(256)
void tohalf_kernel(const float* __restrict__ in, __half* __restrict__ out, int n4)
{
    int i = blockIdx.x * blockDim.x + threadIdx.x;
    if (i >= n4) return;
    float4 v = ((const float4*)in)[i];
    uint32_t p0 = pack2h(v.x, v.y);
    uint32_t p1 = pack2h(v.z, v.w);
    ((uint2*)out)[i] = make_uint2(p0, p1);
}

// ---------------------------------------------------------------------------
// Transpose + convert: W [K][N] fp32 -> WT [N][K] fp16
// ---------------------------------------------------------------------------
__global__ __launch_bounds__(256)
void transpose_half_kernel(const float* __restrict__ W,
                           __half* __restrict__ WT, int K, int N)
{
    __shared__ float t[32][33];
    int n0 = blockIdx.x * 32;
    int k0 = blockIdx.y * 32;
    int tx = threadIdx.x, ty = threadIdx.y;   // 32 x 8
    #pragma unroll
    for (int r = 0; r < 32; r += 8)
        t[ty + r][tx] = W[(size_t)(k0 + ty + r) * N + n0 + tx];
    __syncthreads();
    #pragma unroll
    for (int r = 0; r < 32; r += 8)
        WT[(size_t)(n0 + ty + r) * K + k0 + tx] = __float2half_rn(t[tx][ty + r]);
}

// ---------------------------------------------------------------------------
// Plain fp16 mma.sync GEMM:  C = A·B^T + bias
// GBK=64 per stage (A,B each 128 rows x 128B swizzled = 16KB), 3 stages,
// interleaved prefetch (8 slices/chunk), tile 128x128, 256 thr, 2 CTAs/SM.
// ---------------------------------------------------------------------------
#define GBM 128
#define GBN 128
#define GBK 64
#define TKB 32768                      // stage bytes (16KB A + 16KB B)
#define NSTAGE 3
#define GEMM_SMEM_BYTES (NSTAGE * TKB) // 98304 B

__global__ __launch_bounds__(256, 2)
void gemm_fp16(const __half* __restrict__ A_g,
               const __half* __restrict__ B_g,
               const float* __restrict__ bias,
               float* __restrict__ Cf,
               __half* __restrict__ Ch,
               int M, int N, int K)
{
    extern __shared__ char smem[];
    const uint32_t smem32 = (uint32_t)__cvta_generic_to_shared(smem);
    const int tid  = threadIdx.x;
    const int bm   = blockIdx.y * GBM;
    const int bn   = blockIdx.x * GBN;
    const int warp = tid >> 5, lane = tid & 31;
    const int wm   = (warp & 1) * 64;
    const int wn   = (warp >> 1) * 32;

    float acc[4][4][4];
    #pragma unroll
    for (int i = 0; i < 4; ++i)
        #pragma unroll
        for (int j = 0; j < 4; ++j)
            #pragma unroll
            for (int r = 0; r < 4; ++r) acc[i][j][r] = 0.f;

    // slice p in 0..7: p<4 -> A quarter p, p>=4 -> B quarter p-4. 1 cp16/thread.
    auto load_part = [&](int s, int k0, int p) {
        uint32_t st = smem32 + s * TKB;
        int c = tid + (p & 3) * 256;      // 0..1023 over 128 rows x 8 chunks
        int row = c >> 3, cc = c & 7;
        uint32_t d = (p < 4 ? st : st + 16384)
                   + row * 128 + ((cc ^ (row & 7)) * 16);
        const __half* src = (p < 4)
            ? A_g + (size_t)(bm + row) * K + k0 + cc * 8
            : B_g + (size_t)(bn + row) * K + k0 + cc * 8;
        cp16r(d, src);
    };

    const int niter = K / GBK;
    #pragma unroll
    for (int p = 0; p < 8; ++p) load_part(0, 0, p);
    cp_commit();
    #pragma unroll
    for (int p = 0; p < 8; ++p) load_part(1, GBK, p);
    cp_commit();

    const int arow0 = wm + (lane & 15);
    const int brow0 = wn + (lane & 7);
    const int ac0   = lane >> 4;          // A k-halfslice bit (chunk bit0)
    const int bc0   = (lane >> 3) & 1;

    int sc = 0, sn = 2;
    for (int it = 0; it < niter; ++it) {
        if (it + 1 < niter) cp_wait<1>(); else cp_wait<0>();
        __syncthreads();

        uint32_t aab = smem32 + sc * TKB;
        uint32_t aA[4], bA[4];
        #pragma unroll
        for (int mt = 0; mt < 4; ++mt) {
            int row = arow0 + mt * 16;
            aA[mt] = aab + row * 128 + ((ac0 ^ (row & 7)) * 16);
        }
        #pragma unroll
        for (int nt = 0; nt < 4; ++nt) {
            int row = brow0 + nt * 8;
            bA[nt] = aab + 16384 + row * 128 + ((bc0 ^ (row & 7)) * 16);
        }

        const bool pf  = (it + 2 < niter);
        const int  nk0 = (it + 2) * GBK;

        #pragma unroll
        for (int ks = 0; ks < 4; ++ks) {
            const uint32_t ko = ks * 32;   // chunk pair 2ks -> byte XOR (bits 5-6)

            uint32_t bf[4][2];
            #pragma unroll
            for (int nt = 0; nt < 4; ++nt)
                ldm_x2r(bf[nt], bA[nt] ^ ko);

            #pragma unroll
            for (int mt = 0; mt < 4; ++mt) {
                uint32_t af[4];
                ldm_x4r(af, aA[mt] ^ ko);
                if (pf && mt == 1) load_part(sn, nk0, ks);       // A slice
                if (pf && mt == 3) load_part(sn, nk0, 4 + ks);   // B slice
                #pragma unroll
                for (int nt = 0; nt < 4; ++nt)
                    mma_fp16(acc[mt][nt], af, bf[nt]);
            }
        }
        if (pf) cp_commit();
        sc = (sc + 1 == NSTAGE) ? 0 : sc + 1;
        sn = (sn + 1 == NSTAGE) ? 0 : sn + 1;
    }

    // Epilogue: bias + store (fp32 out, or fp16)
    #pragma unroll
    for (int mt = 0; mt < 4; ++mt) {
        int r0 = bm + wm + mt * 16 + (lane >> 2);
        #pragma unroll
        for (int nt = 0; nt < 4; ++nt) {
            int cc = bn + wn + nt * 8 + (lane & 3) * 2;
            float b0 = bias[cc], b1 = bias[cc + 1];
            float v0 = acc[mt][nt][0] + b0, v1 = acc[mt][nt][1] + b1;
            float v2 = acc[mt][nt][2] + b0, v3 = acc[mt][nt][3] + b1;
            if (Cf) {
                *(float2*)(Cf + (size_t)r0 * N + cc)       = make_float2(v0, v1);
                *(float2*)(Cf + (size_t)(r0 + 8) * N + cc) = make_float2(v2, v3);
            } else {
                *(uint32_t*)(Ch + (size_t)r0 * N + cc)       = pack2h(v0, v1);
                *(uint32_t*)(Ch + (size_t)(r0 + 8) * N + cc) = pack2h(v2, v3);
            }
        }
    }
}

// ---------------------------------------------------------------------------
// Plain fp16 causal flash attention, BQ=128 (8 warps, 256 thr), 2 CTAs/SM.
//   S = Q·K^T, O = P·V  (all fp16 operands, fp32 accumulate)
// ---------------------------------------------------------------------------
#define AROW  72
#define QTILE (128 * AROW)
#define KTILE (64 * AROW)
#define ASTG  (2 * KTILE)                           // K, V per stage
#define FLASH_SMEM_BYTES ((QTILE + 2 * ASTG) * 2)   // 55296 B

__global__ __launch_bounds__(256, 2)
void flash_attn_tc(const __half* __restrict__ qkv,
                   __half* __restrict__ y)
{
    extern __shared__ __half sm[];
    __half* Qs = sm;
    __half* KV = sm + QTILE;

    const int qb = gridDim.x - 1 - blockIdx.x;
    const int h  = blockIdx.y;
    const int b  = blockIdx.z;
    const int q0 = qb * 128;
    const int tid = threadIdx.x, warp = tid >> 5, lane = tid & 31;

    const size_t rstride = (size_t)3 * CDIM;
    const size_t base = (size_t)b * T_SEQ * rstride + (size_t)h * HD;

    for (int i = tid; i < 1024; i += 256) {
        int r = i >> 3, ch = i & 7;
        cp16(Qs + r * AROW + ch * 8, qkv + base + (size_t)(q0 + r) * rstride + ch * 8);
    }
    cp_commit();

    auto load_kv = [&](int s, int k0) {
        __half* Kh = KV + s * ASTG;
        __half* Vh = Kh + KTILE;
        for (int i = tid; i < 512; i += 256) {
            int r = i >> 3, ch = i & 7;
            size_t gk = base + CDIM + (size_t)(k0 + r) * rstride + ch * 8;
            cp16(Kh + r * AROW + ch * 8, qkv + gk);
            cp16(Vh + r * AROW + ch * 8, qkv + gk + CDIM);
        }
    };
    load_kv(0, 0);
    cp_commit();

    float o[8][4];
    #pragma unroll
    for (int nb = 0; nb < 8; ++nb)
        #pragma unroll
        for (int r = 0; r < 4; ++r) o[nb][r] = 0.f;
    float m0 = -1e30f, m1 = -1e30f, l0 = 0.f, l1 = 0.f;

    const float SC = 0.125f * 1.4426950408889634f;
    const int rin   = lane >> 2;
    const int qrow0 = q0 + warp * 16 + rin;
    const int qrow1 = qrow0 + 8;
    const int cbase = 2 * (lane & 3);

    const int krow_x4 = ((lane >> 4) & 1) * 8 + (lane & 7);
    const int kcol_x4 = ((lane >> 3) & 1) * 8;
    const int vrow_x4 = lane & 15;
    const int vcol_x4 = ((lane >> 4) & 1) * 8;

    const int nkt = 2 * qb + 2;
    for (int kt = 0; kt < nkt; ++kt) {
        cp_wait<0>();
        __syncthreads();
        if (kt + 1 < nkt) { load_kv((kt + 1) & 1, (kt + 1) * 64); cp_commit(); }

        const __half* Kh = KV + (kt & 1) * ASTG;
        const __half* Vh = Kh + KTILE;

        float s[8][4];
        #pragma unroll
        for (int nb = 0; nb < 8; ++nb)
            #pragma unroll
            for (int r = 0; r < 4; ++r) s[nb][r] = 0.f;

        // ---- S = Q K^T ----
        #pragma unroll
        for (int ks = 0; ks < 4; ++ks) {
            const int aoff = (warp * 16 + (lane & 15)) * AROW + ks * 16 + (lane >> 4) * 8;
            uint32_t ah[4];
            ldm_x4(ah, Qs + aoff);
            #pragma unroll
            for (int nbp = 0; nbp < 4; ++nbp) {
                const int koff = (nbp * 16 + krow_x4) * AROW + ks * 16 + kcol_x4;
                uint32_t kh[4];
                ldm_x4(kh, Kh + koff);
                mma_fp16(s[2*nbp  ], ah, &kh[0]);
                mma_fp16(s[2*nbp+1], ah, &kh[2]);
            }
        }

        const int k0 = kt * 64;
        if (kt >= 2 * qb) {
            #pragma unroll
            for (int nb = 0; nb < 8; ++nb) {
                int c0 = k0 + nb * 8 + cbase;
                s[nb][0] = (c0     <= qrow0) ? s[nb][0] * SC : -1e30f;
                s[nb][1] = (c0 + 1 <= qrow0) ? s[nb][1] * SC : -1e30f;
                s[nb][2] = (c0     <= qrow1) ? s[nb][2] * SC : -1e30f;
                s[nb][3] = (c0 + 1 <= qrow1) ? s[nb][3] * SC : -1e30f;
            }
        } else {
            #pragma unroll
            for (int nb = 0; nb < 8; ++nb)
                #pragma unroll
                for (int r = 0; r < 4; ++r) s[nb][r] *= SC;
        }

        float mx0 = -1e30f, mx1 = -1e30f;
        #pragma unroll
        for (int nb = 0; nb < 8; ++nb) {
            mx0 = fmaxf(mx0, fmaxf(s[nb][0], s[nb][1]));
            mx1 = fmaxf(mx1, fmaxf(s[nb][2], s[nb][3]));
        }
        mx0 = fmaxf(mx0, __shfl_xor_sync(0xffffffffu, mx0, 1));
        mx0 = fmaxf(mx0, __shfl_xor_sync(0xffffffffu, mx0, 2));
        mx1 = fmaxf(mx1, __shfl_xor_sync(0xffffffffu, mx1, 1));
        mx1 = fmaxf(mx1, __shfl_xor_sync(0xffffffffu, mx1, 2));

        float nm0 = fmaxf(m0, mx0), nm1 = fmaxf(m1, mx1);
        float sc0 = exp2f(m0 - nm0), sc1 = exp2f(m1 - nm1);
        m0 = nm0; m1 = nm1;

        float rs0 = 0.f, rs1 = 0.f;
        #pragma unroll
        for (int nb = 0; nb < 8; ++nb) {
            s[nb][0] = exp2f(s[nb][0] - nm0);
            s[nb][1] = exp2f(s[nb][1] - nm0);
            s[nb][2] = exp2f(s[nb][2] - nm1);
            s[nb][3] = exp2f(s[nb][3] - nm1);
            rs0 += s[nb][0] + s[nb][1];
            rs1 += s[nb][2] + s[nb][3];
        }

        #pragma unroll
        for (int nb = 0; nb < 8; ++nb) {
            o[nb][0] *= sc0; o[nb][1] *= sc0;
            o[nb][2] *= sc1; o[nb][3] *= sc1;
        }

        // ---- O += P V ----
        #pragma unroll
        for (int t = 0; t < 4; ++t) {
            uint32_t ph[4];
            ph[0] = pack2h(s[2*t  ][0], s[2*t  ][1]);
            ph[1] = pack2h(s[2*t  ][2], s[2*t  ][3]);
            ph[2] = pack2h(s[2*t+1][0], s[2*t+1][1]);
            ph[3] = pack2h(s[2*t+1][2], s[2*t+1][3]);
            const int vbase = (t * 16 + vrow_x4) * AROW;
            #pragma unroll
            for (int nbp = 0; nbp < 4; ++nbp) {
                const int voff = vbase + nbp * 16 + vcol_x4;
                uint32_t vh[4];
                ldm_x4t(vh, Vh + voff);
                mma_fp16(o[2*nbp  ], ph, &vh[0]);
                mma_fp16(o[2*nbp+1], ph, &vh[2]);
            }
        }

        rs0 += __shfl_xor_sync(0xffffffffu, rs0, 1);
        rs0 += __shfl_xor_sync(0xffffffffu, rs0, 2);
        rs1 += __shfl_xor_sync(0xffffffffu, rs1, 1);
        rs1 += __shfl_xor_sync(0xffffffffu, rs1, 2);
        l0 = l0 * sc0 + rs0;
        l1 = l1 * sc1 + rs1;
    }

    float inv0 = 1.f / l0, inv1 = 1.f / l1;
    const size_t row0 = (size_t)b * T_SEQ + qrow0;
    const size_t row1 = (size_t)b * T_SEQ + qrow1;
    #pragma unroll
    for (int nb = 0; nb < 8; ++nb) {
        int cc = h * HD + nb * 8 + cbase;
        *(uint32_t*)(y + row0 * CDIM + cc) = pack2h(o[nb][0] * inv0, o[nb][1] * inv0);
        *(uint32_t*)(y + row1 * CDIM + cc) = pack2h(o[nb][2] * inv1, o[nb][3] * inv1);
    }
}

// ---------------------------------------------------------------------------
// kernel_launch
// ---------------------------------------------------------------------------
extern "C" void kernel_launch(void* const* d_in, const int* in_sizes, int n_in,
                              void* d_out, int out_size)
{
    (void)in_sizes; (void)n_in; (void)out_size;
    const float* x      = (const float*)d_in[0];
    const float* W_attn = (const float*)d_in[1];
    const float* b_attn = (const float*)d_in[2];
    const float* W_proj = (const float*)d_in[3];
    const float* b_proj = (const float*)d_in[4];
    float* out = (float*)d_out;

    __half *x16, *qkv16, *y16, *wa, *wp;
    cudaGetSymbolAddress((void**)&x16,   g_x16);
    cudaGetSymbolAddress((void**)&qkv16, g_qkv16);
    cudaGetSymbolAddress((void**)&y16,   g_y16);
    cudaGetSymbolAddress((void**)&wa,    g_wa);
    cudaGetSymbolAddress((void**)&wp,    g_wp);

    cudaFuncSetAttribute(gemm_fp16, cudaFuncAttributeMaxDynamicSharedMemorySize,
                         GEMM_SMEM_BYTES);
    cudaFuncSetAttribute(flash_attn_tc, cudaFuncAttributeMaxDynamicSharedMemorySize,
                         FLASH_SMEM_BYTES);

    // 1) x -> fp16
    {
        int n4 = MROWS * CDIM / 4;
        tohalf_kernel<<<(n4 + 255) / 256, 256>>>(x, x16, n4);
    }
    // 2) transpose + convert weights
    {
        dim3 blk(32, 8);
        transpose_half_kernel<<<dim3(3 * CDIM / 32, CDIM / 32), blk>>>(W_attn, wa, CDIM, 3 * CDIM);
        transpose_half_kernel<<<dim3(CDIM / 32, CDIM / 32), blk>>>(W_proj, wp, CDIM, CDIM);
    }
    // 3) qkv(fp16) = x @ W_attn + b_attn   [8192, 3072]
    {
        dim3 grid(3 * CDIM / GBN, MROWS / GBM);   // (24, 64)
        gemm_fp16<<<grid, 256, GEMM_SMEM_BYTES>>>(x16, wa, b_attn,
                                                  nullptr, qkv16,
                                                  MROWS, 3 * CDIM, CDIM);
    }
    // 4) fp16 flash attention -> y16
    {
        dim3 grid(T_SEQ / 128, NHEAD, BATCH);
        flash_attn_tc<<<grid, 256, FLASH_SMEM_BYTES>>>(qkv16, y16);
    }
    // 5) out = y @ W_proj + b_proj   [8192, 1024] fp32
    {
        dim3 grid(CDIM / GBN, MROWS / GBM);       // (8, 64)
        gemm_fp16<<<grid, 256, GEMM_SMEM_BYTES>>>(y16, wp, b_proj,
                                                  out, nullptr,
                                                  MROWS, CDIM, CDIM);
    }
}